// round 12
// baseline (speedup 1.0000x reference)
#include <cuda_runtime.h>
#include <cstdint>

// ---------------------------------------------------------------------------
// Fixed dataset: N=50000, E=800000, IN=128, L1: 4 heads x 64, L2: 1 head x 64.
// edge_index is int32: ei[0:E]=src, ei[E:2E]=dst. Self-loops handled in-warp.
// ---------------------------------------------------------------------------
#define NMAX 50000
#define EMAX 810000

__device__ __align__(16) float g_h1 [NMAX * 256];  // layer1 linear output
__device__ __align__(16) float g_hm [NMAX * 256];  // layer1 GAT output (tf32-rounded)
__device__ __align__(16) float g_h2 [NMAX * 64];   // layer2 linear output
__device__ __align__(16) float g_as1[NMAX * 4];
__device__ __align__(16) float g_ad1[NMAX * 4];
__device__ __align__(16) float g_as2[NMAX];
__device__ __align__(16) float g_ad2[NMAX];
// CSR by dst
__device__ int g_cnt [NMAX];
__device__ int g_rp  [NMAX + 1];
__device__ int g_cur [NMAX];
__device__ int g_col [EMAX];

__device__ __forceinline__ float lrelu(float x) { return x > 0.f ? x : 0.2f * x; }
__device__ __forceinline__ float elu(float x)   { return x > 0.f ? x : expm1f(x); }
__device__ __forceinline__ uint32_t to_tf32(float x) {
    uint32_t r;
    asm("cvt.rna.tf32.f32 %0, %1;" : "=r"(r) : "f"(x));
    return r;
}
__device__ __forceinline__ float tf32f(float x) { return __uint_as_float(to_tf32(x)); }
__device__ __forceinline__ void cp16(uint32_t saddr, const void* gaddr) {
    asm volatile("cp.async.cg.shared.global [%0], [%1], 16;" :: "r"(saddr), "l"(gaddr));
}
__device__ __forceinline__ uint32_t sm_u32(const void* p) {
    return (uint32_t)__cvta_generic_to_shared(p);
}

// ---------------------------------------------------------------------------
// CSR build — 4 edges/thread for MLP (these kernels are LDG->ATOMG
// latency-bound: R4 profile showed occ 78%, issue 4.6%).
// ---------------------------------------------------------------------------
__global__ void count_kernel(const int* __restrict__ ei, int* cnt, int E) {
    int i = blockIdx.x * blockDim.x + threadIdx.x;
    int E4 = E >> 2;
    if (i < E4) {
        int4 d = ((const int4*)(ei + E))[i];
        atomicAdd(cnt + d.x, 1);
        atomicAdd(cnt + d.y, 1);
        atomicAdd(cnt + d.z, 1);
        atomicAdd(cnt + d.w, 1);
    } else if (i == E4) {
        for (int e = E4 * 4; e < E; e++) atomicAdd(cnt + ei[E + e], 1);
    }
}

__global__ void scan_kernel(const int* __restrict__ cnt, int* rp, int* cur, int N) {
    __shared__ int sums[1024];
    int t = threadIdx.x;
    int C = (N + 1023) / 1024;
    int b0 = t * C, b1 = min(N, b0 + C);
    int s = 0;
    for (int i = b0; i < b1; i++) s += cnt[i];
    sums[t] = s;
    __syncthreads();
    for (int off = 1; off < 1024; off <<= 1) {
        int v = (t >= off) ? sums[t - off] : 0;
        __syncthreads();
        sums[t] += v;
        __syncthreads();
    }
    int run = (t == 0) ? 0 : sums[t - 1];
    for (int i = b0; i < b1; i++) { rp[i] = run; cur[i] = run; run += cnt[i]; }
    if (b0 < N && b1 == N) rp[N] = run;
}

__global__ void fill_kernel(const int* __restrict__ ei, int* cur, int* col, int E) {
    int i = blockIdx.x * blockDim.x + threadIdx.x;
    int E4 = E >> 2;
    if (i < E4) {
        int4 s = ((const int4*)ei)[i];
        int4 d = ((const int4*)(ei + E))[i];
        int p0 = atomicAdd(cur + d.x, 1);
        int p1 = atomicAdd(cur + d.y, 1);
        int p2 = atomicAdd(cur + d.z, 1);
        int p3 = atomicAdd(cur + d.w, 1);
        col[p0] = s.x; col[p1] = s.y; col[p2] = s.z; col[p3] = s.w;
    } else if (i == E4) {
        for (int e = E4 * 4; e < E; e++) {
            int pos = atomicAdd(cur + ei[E + e], 1);
            col[pos] = ei[e];
        }
    }
}

// ---------------------------------------------------------------------------
// TF32 GEMM, cp.async double-buffered.
// CVTA/CVTB: round A/B tiles to tf32 (RNA) in smem after arrival, so raw
// fp32 inputs need no pre-pass. C[M,Nc] = A[M,K] @ B[K,Nc].
// Block 128x64, BK=32, 8 warps, warp tile 32x32 via mma.m16n8k8.
// Fused attention-scalar epilogue (head = blockIdx.x, 64 channels).
// ---------------------------------------------------------------------------
#define AKP 36
#define BNP 72
#define A_STAGE (128 * AKP)
#define B_STAGE (32 * BNP)
#define STAGE   (A_STAGE + B_STAGE)
#define GEMM_SMEM (2 * STAGE * 4)

template <bool CVTA, bool CVTB>
__global__ __launch_bounds__(256, 3) void tf32_gemm(
    int M, int Nc, int K,
    const float* __restrict__ A, const float* __restrict__ B, float* __restrict__ C,
    const float* __restrict__ att_s, const float* __restrict__ att_d,
    float* __restrict__ asrc, float* __restrict__ adst, int astride)
{
    extern __shared__ uint32_t smem[];
    __shared__ float s_ps[2][128];
    __shared__ float s_pd[2][128];

    const int tid    = threadIdx.x;
    const int lane   = tid & 31;
    const int wid    = tid >> 5;
    const int warp_m = wid & 3;
    const int warp_n = wid >> 2;
    const int bn0    = blockIdx.x * 64;
    const int bm0    = blockIdx.y * 128;

    float acc[2][4][4];
#pragma unroll
    for (int i = 0; i < 2; i++)
#pragma unroll
        for (int j = 0; j < 4; j++)
#pragma unroll
            for (int k = 0; k < 4; k++) acc[i][j][k] = 0.f;

    const int rA = lane >> 2;
    const int cA = lane & 3;

    auto issue = [&](int k0, int p) {
        uint32_t* Asb = smem + p * STAGE;
        uint32_t* Bsb = Asb + A_STAGE;
#pragma unroll
        for (int t = 0; t < 4; t++) {
            int i = tid + t * 256, r = i >> 3, c = (i & 7) * 4;
            int gr = bm0 + r;
            if (gr < M) cp16(sm_u32(&Asb[r * AKP + c]), A + (size_t)gr * K + k0 + c);
            else        *(uint4*)&Asb[r * AKP + c] = make_uint4(0, 0, 0, 0);
        }
#pragma unroll
        for (int t = 0; t < 2; t++) {
            int i = tid + t * 256, r = i >> 4, c = (i & 15) * 4;
            cp16(sm_u32(&Bsb[r * BNP + c]), B + (size_t)(k0 + r) * Nc + bn0 + c);
        }
        asm volatile("cp.async.commit_group;");
    };

    const int T = K / 32;
    issue(0, 0);

    for (int t = 0; t < T; t++) {
        int p = t & 1;
        if (t + 1 < T) {
            issue((t + 1) * 32, 1 - p);
            asm volatile("cp.async.wait_group 1;");
        } else {
            asm volatile("cp.async.wait_group 0;");
        }
        __syncthreads();

        uint32_t* Asb = smem + p * STAGE;
        uint32_t* Bsb = Asb + A_STAGE;

        if (CVTA || CVTB) {
            if (CVTA) {
#pragma unroll
                for (int tt = 0; tt < 4; tt++) {
                    int i = tid + tt * 256, r = i >> 3, c = (i & 7) * 4;
                    uint4 u = *(uint4*)&Asb[r * AKP + c];
                    u.x = to_tf32(__uint_as_float(u.x));
                    u.y = to_tf32(__uint_as_float(u.y));
                    u.z = to_tf32(__uint_as_float(u.z));
                    u.w = to_tf32(__uint_as_float(u.w));
                    *(uint4*)&Asb[r * AKP + c] = u;
                }
            }
            if (CVTB) {
#pragma unroll
                for (int tt = 0; tt < 2; tt++) {
                    int i = tid + tt * 256, r = i >> 4, c = (i & 15) * 4;
                    uint4 u = *(uint4*)&Bsb[r * BNP + c];
                    u.x = to_tf32(__uint_as_float(u.x));
                    u.y = to_tf32(__uint_as_float(u.y));
                    u.z = to_tf32(__uint_as_float(u.z));
                    u.w = to_tf32(__uint_as_float(u.w));
                    *(uint4*)&Bsb[r * BNP + c] = u;
                }
            }
            __syncthreads();
        }

#pragma unroll
        for (int kk = 0; kk < 32; kk += 8) {
            uint32_t a[2][4];
#pragma unroll
            for (int mf = 0; mf < 2; mf++) {
                int r0 = warp_m * 32 + mf * 16 + rA;
                a[mf][0] = Asb[(r0    ) * AKP + kk + cA];
                a[mf][1] = Asb[(r0 + 8) * AKP + kk + cA];
                a[mf][2] = Asb[(r0    ) * AKP + kk + cA + 4];
                a[mf][3] = Asb[(r0 + 8) * AKP + kk + cA + 4];
            }
            uint32_t b[4][2];
#pragma unroll
            for (int nf = 0; nf < 4; nf++) {
                int n0 = warp_n * 32 + nf * 8 + rA;
                b[nf][0] = Bsb[(kk + cA    ) * BNP + n0];
                b[nf][1] = Bsb[(kk + cA + 4) * BNP + n0];
            }
#pragma unroll
            for (int mf = 0; mf < 2; mf++)
#pragma unroll
                for (int nf = 0; nf < 4; nf++) {
                    asm volatile(
                        "mma.sync.aligned.m16n8k8.row.col.f32.tf32.tf32.f32 "
                        "{%0,%1,%2,%3}, {%4,%5,%6,%7}, {%8,%9}, {%0,%1,%2,%3};"
                        : "+f"(acc[mf][nf][0]), "+f"(acc[mf][nf][1]),
                          "+f"(acc[mf][nf][2]), "+f"(acc[mf][nf][3])
                        : "r"(a[mf][0]), "r"(a[mf][1]), "r"(a[mf][2]), "r"(a[mf][3]),
                          "r"(b[nf][0]), "r"(b[nf][1]));
                }
        }
        __syncthreads();
    }

    // Store C
#pragma unroll
    for (int mf = 0; mf < 2; mf++) {
        int r0 = bm0 + warp_m * 32 + mf * 16 + rA;
#pragma unroll
        for (int nf = 0; nf < 4; nf++) {
            int cc = bn0 + warp_n * 32 + nf * 8 + cA * 2;
            if (r0 < M)
                *(float2*)(C + (size_t)r0 * Nc + cc)
                    = make_float2(acc[mf][nf][0], acc[mf][nf][1]);
            if (r0 + 8 < M)
                *(float2*)(C + (size_t)(r0 + 8) * Nc + cc)
                    = make_float2(acc[mf][nf][2], acc[mf][nf][3]);
        }
    }

    // Fused attention scalars for head blockIdx.x
    const int hb = blockIdx.x * 64;
    float ps[2][2] = {{0.f,0.f},{0.f,0.f}}, pd[2][2] = {{0.f,0.f},{0.f,0.f}};
#pragma unroll
    for (int mf = 0; mf < 2; mf++)
#pragma unroll
        for (int nf = 0; nf < 4; nf++) {
            int cloc = warp_n * 32 + nf * 8 + cA * 2;
            float a_s0 = __ldg(att_s + hb + cloc), a_s1 = __ldg(att_s + hb + cloc + 1);
            float a_d0 = __ldg(att_d + hb + cloc), a_d1 = __ldg(att_d + hb + cloc + 1);
            ps[mf][0] += acc[mf][nf][0] * a_s0 + acc[mf][nf][1] * a_s1;
            ps[mf][1] += acc[mf][nf][2] * a_s0 + acc[mf][nf][3] * a_s1;
            pd[mf][0] += acc[mf][nf][0] * a_d0 + acc[mf][nf][1] * a_d1;
            pd[mf][1] += acc[mf][nf][2] * a_d0 + acc[mf][nf][3] * a_d1;
        }
#pragma unroll
    for (int mf = 0; mf < 2; mf++)
#pragma unroll
        for (int hh = 0; hh < 2; hh++) {
            ps[mf][hh] += __shfl_xor_sync(0xffffffffu, ps[mf][hh], 1);
            ps[mf][hh] += __shfl_xor_sync(0xffffffffu, ps[mf][hh], 2);
            pd[mf][hh] += __shfl_xor_sync(0xffffffffu, pd[mf][hh], 1);
            pd[mf][hh] += __shfl_xor_sync(0xffffffffu, pd[mf][hh], 2);
        }
    if (cA == 0) {
#pragma unroll
        for (int mf = 0; mf < 2; mf++) {
            int r0 = warp_m * 32 + mf * 16 + rA;
            s_ps[warp_n][r0]     = ps[mf][0];
            s_ps[warp_n][r0 + 8] = ps[mf][1];
            s_pd[warp_n][r0]     = pd[mf][0];
            s_pd[warp_n][r0 + 8] = pd[mf][1];
        }
    }
    __syncthreads();
    if (tid < 128) {
        int gr = bm0 + tid;
        if (gr < M) {
            asrc[(size_t)gr * astride + blockIdx.x] = s_ps[0][tid] + s_ps[1][tid];
            adst[(size_t)gr * astride + blockIdx.x] = s_pd[0][tid] + s_pd[1][tid];
        }
    }
}

// ---------------------------------------------------------------------------
// Layer-1 GAT gather: one warp per dst node. Column indices + weights cached
// in smem during phase A; phase B 4-way unrolled for MLP.
// WCAP=128 (20KB smem/block keeps residency ~5 CTA/SM, which measured best;
// WCAP=64 raised residency and REGRESSED 30% via L1tex-queue contention).
// ---------------------------------------------------------------------------
#define WCAP 128

__global__ __launch_bounds__(256) void gather1_kernel(
    const int* __restrict__ rp, const int* __restrict__ col,
    const float* __restrict__ h1,
    const float* __restrict__ asrc, const float* __restrict__ adst,
    const float* __restrict__ bias, float* __restrict__ out, int N)
{
    __shared__ float s_w[8][WCAP * 4];
    __shared__ int   s_col[8][WCAP];
    int warp = threadIdx.x >> 5, lane = threadIdx.x & 31;
    int d = blockIdx.x * 8 + warp;
    if (d >= N) return;

    int beg = rp[d];
    int deg = rp[d + 1] - beg;
    int hme = lane & 3;
    float ad_hme = __ldg(adst + (size_t)d * 4 + hme);

    float pden = 0.f;
    int npairs = deg * 4;
    for (int idx = lane; idx < npairs; idx += 32) {
        int e = idx >> 2;
        int s = __ldg(col + beg + e);
        float w = __expf(lrelu(__ldg(asrc + (size_t)s * 4 + hme) + ad_hme));
        if (e < WCAP) {
            s_w[warp][idx] = w;
            if (hme == 0) s_col[warp][e] = s;
        }
        pden += w;
    }
    pden += __shfl_xor_sync(0xffffffffu, pden, 4);
    pden += __shfl_xor_sync(0xffffffffu, pden, 8);
    pden += __shfl_xor_sync(0xffffffffu, pden, 16);
    float w_self = __expf(lrelu(__ldg(asrc + (size_t)d * 4 + hme) + ad_hme));
    float inv_den = 1.f / (pden + w_self + 1e-16f);
    __syncwarp();

    int head = lane >> 3;
    float inv_h   = __shfl_sync(0xffffffffu, inv_den, head);
    float aself_h = __shfl_sync(0xffffffffu, w_self,  head) * inv_h;
    float ad_head = __shfl_sync(0xffffffffu, ad_hme,  head);

    float acc[8];
    {
        const float4* hp = (const float4*)(h1 + (size_t)d * 256 + lane * 8);
        float4 v0 = __ldg(hp), v1 = __ldg(hp + 1);
        acc[0]=aself_h*v0.x; acc[1]=aself_h*v0.y; acc[2]=aself_h*v0.z; acc[3]=aself_h*v0.w;
        acc[4]=aself_h*v1.x; acc[5]=aself_h*v1.y; acc[6]=aself_h*v1.z; acc[7]=aself_h*v1.w;
    }

    if (deg <= WCAP) {
        int e = 0;
        for (; e + 4 <= deg; e += 4) {
            int   sx[4];
            float al[4];
#pragma unroll
            for (int q = 0; q < 4; q++) {
                sx[q] = s_col[warp][e + q];
                al[q] = s_w[warp][(e + q) * 4 + head] * inv_h;
            }
            float4 u0[4], u1[4];
#pragma unroll
            for (int q = 0; q < 4; q++) {
                const float4* hp = (const float4*)(h1 + (size_t)sx[q] * 256 + lane * 8);
                u0[q] = __ldg(hp); u1[q] = __ldg(hp + 1);
            }
#pragma unroll
            for (int q = 0; q < 4; q++) {
                acc[0]+=al[q]*u0[q].x; acc[1]+=al[q]*u0[q].y;
                acc[2]+=al[q]*u0[q].z; acc[3]+=al[q]*u0[q].w;
                acc[4]+=al[q]*u1[q].x; acc[5]+=al[q]*u1[q].y;
                acc[6]+=al[q]*u1[q].z; acc[7]+=al[q]*u1[q].w;
            }
        }
        for (; e < deg; e++) {
            int s = s_col[warp][e];
            float alpha = s_w[warp][e * 4 + head] * inv_h;
            const float4* hp = (const float4*)(h1 + (size_t)s * 256 + lane * 8);
            float4 v0 = __ldg(hp), v1 = __ldg(hp + 1);
            acc[0]+=alpha*v0.x; acc[1]+=alpha*v0.y; acc[2]+=alpha*v0.z; acc[3]+=alpha*v0.w;
            acc[4]+=alpha*v1.x; acc[5]+=alpha*v1.y; acc[6]+=alpha*v1.z; acc[7]+=alpha*v1.w;
        }
    } else {
        for (int e = 0; e < deg; e++) {
            int s = __ldg(col + beg + e);
            float w = (e < WCAP) ? s_w[warp][e * 4 + head]
                                 : __expf(lrelu(__ldg(asrc + (size_t)s * 4 + head) + ad_head));
            float alpha = w * inv_h;
            const float4* hp = (const float4*)(h1 + (size_t)s * 256 + lane * 8);
            float4 v0 = __ldg(hp), v1 = __ldg(hp + 1);
            acc[0]+=alpha*v0.x; acc[1]+=alpha*v0.y; acc[2]+=alpha*v0.z; acc[3]+=alpha*v0.w;
            acc[4]+=alpha*v1.x; acc[5]+=alpha*v1.y; acc[6]+=alpha*v1.z; acc[7]+=alpha*v1.w;
        }
    }

    const float4* bp = (const float4*)(bias + lane * 8);
    float4 b0 = __ldg(bp), b1v = __ldg(bp + 1);
    float4 o0, o1;
    o0.x=tf32f(elu(acc[0]+b0.x));  o0.y=tf32f(elu(acc[1]+b0.y));
    o0.z=tf32f(elu(acc[2]+b0.z));  o0.w=tf32f(elu(acc[3]+b0.w));
    o1.x=tf32f(elu(acc[4]+b1v.x)); o1.y=tf32f(elu(acc[5]+b1v.y));
    o1.z=tf32f(elu(acc[6]+b1v.z)); o1.w=tf32f(elu(acc[7]+b1v.w));
    float4* op = (float4*)(out + (size_t)d * 256 + lane * 8);
    op[0] = o0; op[1] = o1;
}

// ---------------------------------------------------------------------------
// Layer-2 GAT gather + final epilogue.
// ---------------------------------------------------------------------------
__global__ __launch_bounds__(256) void gather2_kernel(
    const int* __restrict__ rp, const int* __restrict__ col,
    const float* __restrict__ h2,
    const float* __restrict__ asrc, const float* __restrict__ adst,
    const float* __restrict__ b2, const float* __restrict__ Ws,
    const float* __restrict__ bs, float* __restrict__ out, int N)
{
    __shared__ float s_w[8][WCAP];
    __shared__ int   s_col[8][WCAP];
    int warp = threadIdx.x >> 5, lane = threadIdx.x & 31;
    int d = blockIdx.x * 8 + warp;
    if (d >= N) return;

    int beg = rp[d];
    int deg = rp[d + 1] - beg;
    float adv = __ldg(adst + d);

    float pden = 0.f;
    for (int e = lane; e < deg; e += 32) {
        int s = __ldg(col + beg + e);
        float w = __expf(lrelu(__ldg(asrc + s) + adv));
        if (e < WCAP) { s_w[warp][e] = w; s_col[warp][e] = s; }
        pden += w;
    }
#pragma unroll
    for (int off = 16; off; off >>= 1) pden += __shfl_xor_sync(0xffffffffu, pden, off);
    float w_self = __expf(lrelu(__ldg(asrc + d) + adv));
    float inv_den = 1.f / (pden + w_self + 1e-16f);
    __syncwarp();

    float2 acc;
    {
        float2 v = __ldg((const float2*)(h2 + (size_t)d * 64) + lane);
        float a = w_self * inv_den;
        acc.x = a * v.x; acc.y = a * v.y;
    }
    if (deg <= WCAP) {
        int e = 0;
        for (; e + 4 <= deg; e += 4) {
            int sx[4]; float al[4]; float2 v[4];
#pragma unroll
            for (int q = 0; q < 4; q++) {
                sx[q] = s_col[warp][e + q];
                al[q] = s_w[warp][e + q] * inv_den;
            }
#pragma unroll
            for (int q = 0; q < 4; q++)
                v[q] = __ldg((const float2*)(h2 + (size_t)sx[q] * 64) + lane);
#pragma unroll
            for (int q = 0; q < 4; q++) {
                acc.x += al[q] * v[q].x; acc.y += al[q] * v[q].y;
            }
        }
        for (; e < deg; e++) {
            int s = s_col[warp][e];
            float alpha = s_w[warp][e] * inv_den;
            float2 v = __ldg((const float2*)(h2 + (size_t)s * 64) + lane);
            acc.x += alpha * v.x; acc.y += alpha * v.y;
        }
    } else {
        for (int e = 0; e < deg; e++) {
            int s = __ldg(col + beg + e);
            float w = (e < WCAP) ? s_w[warp][e]
                                 : __expf(lrelu(__ldg(asrc + s) + adv));
            float alpha = w * inv_den;
            float2 v = __ldg((const float2*)(h2 + (size_t)s * 64) + lane);
            acc.x += alpha * v.x; acc.y += alpha * v.y;
        }
    }
    float o0 = elu(acc.x + __ldg(b2 + lane * 2));
    float o1 = elu(acc.y + __ldg(b2 + lane * 2 + 1));
    *(float2*)(out + (size_t)d * 64 + lane * 2) = make_float2(o0, o1);
    float sc = o0 * __ldg(Ws + lane * 2) + o1 * __ldg(Ws + lane * 2 + 1);
#pragma unroll
    for (int off = 16; off; off >>= 1) sc += __shfl_xor_sync(0xffffffffu, sc, off);
    if (lane == 0) out[(size_t)N * 64 + d] = sc + __ldg(bs);
}

// ---------------------------------------------------------------------------
// Launch
// ---------------------------------------------------------------------------
extern "C" void kernel_launch(void* const* d_in, const int* in_sizes, int n_in,
                              void* d_out, int out_size)
{
    const float* x   = (const float*)d_in[0];
    const int*   ei  = (const int*)d_in[1];
    const float* W1  = (const float*)d_in[2];
    const float* as1 = (const float*)d_in[3];
    const float* ad1 = (const float*)d_in[4];
    const float* b1  = (const float*)d_in[5];
    const float* W2  = (const float*)d_in[6];
    const float* as2 = (const float*)d_in[7];
    const float* ad2 = (const float*)d_in[8];
    const float* b2  = (const float*)d_in[9];
    const float* Ws  = (const float*)d_in[10];
    const float* bs  = (const float*)d_in[11];
    float*       out = (float*)d_out;

    const int N = in_sizes[0] / 128;
    const int E = in_sizes[1] / 2;

    float *h1, *hm, *h2, *as1p, *ad1p, *as2p, *ad2p;
    int *cnt, *rp, *cur, *colp;
    cudaGetSymbolAddress((void**)&h1,   g_h1);
    cudaGetSymbolAddress((void**)&hm,   g_hm);
    cudaGetSymbolAddress((void**)&h2,   g_h2);
    cudaGetSymbolAddress((void**)&as1p, g_as1);
    cudaGetSymbolAddress((void**)&ad1p, g_ad1);
    cudaGetSymbolAddress((void**)&as2p, g_as2);
    cudaGetSymbolAddress((void**)&ad2p, g_ad2);
    cudaGetSymbolAddress((void**)&cnt,  g_cnt);
    cudaGetSymbolAddress((void**)&rp,   g_rp);
    cudaGetSymbolAddress((void**)&cur,  g_cur);
    cudaGetSymbolAddress((void**)&colp, g_col);

    static cudaStream_t s2 = nullptr;
    static cudaEvent_t evFork = nullptr, evJoin = nullptr;
    static bool attrSet = false;
    if (!s2) {
        cudaStreamCreateWithFlags(&s2, cudaStreamNonBlocking);
        cudaEventCreateWithFlags(&evFork, cudaEventDisableTiming);
        cudaEventCreateWithFlags(&evJoin, cudaEventDisableTiming);
    }
    if (!attrSet) {
        cudaFuncSetAttribute((const void*)tf32_gemm<true, true>,
                             cudaFuncAttributeMaxDynamicSharedMemorySize, GEMM_SMEM);
        cudaFuncSetAttribute((const void*)tf32_gemm<false, true>,
                             cudaFuncAttributeMaxDynamicSharedMemorySize, GEMM_SMEM);
        attrSet = true;
    }

    // Fork: CSR build on s2, concurrent with layer-1 GEMM.
    cudaEventRecord(evFork, 0);
    cudaStreamWaitEvent(s2, evFork, 0);
    cudaMemsetAsync(cnt, 0, (size_t)N * sizeof(int), s2);
    int E4 = E >> 2;
    count_kernel<<<(E4 + 256) / 256, 256, 0, s2>>>(ei, cnt, E);
    scan_kernel<<<1, 1024, 0, s2>>>(cnt, rp, cur, N);
    fill_kernel<<<(E4 + 256) / 256, 256, 0, s2>>>(ei, cur, colp, E);
    cudaEventRecord(evJoin, s2);

    // Layer 1 GEMM (+fused att scalars); raw x and W1 rounded in-kernel.
    tf32_gemm<true, true><<<dim3(4, (N + 127) / 128), 256, GEMM_SMEM>>>(
        N, 256, 128, x, W1, h1, as1, ad1, as1p, ad1p, 4);

    cudaStreamWaitEvent(0, evJoin, 0);
    gather1_kernel<<<(N + 7) / 8, 256>>>(rp, colp, h1, as1p, ad1p, b1, hm, N);

    // Layer 2: hm pre-rounded by gather1; raw W2 rounded in-kernel.
    tf32_gemm<false, true><<<dim3(1, (N + 127) / 128), 256, GEMM_SMEM>>>(
        N, 64, 256, hm, W2, h2, as2, ad2, as2p, ad2p, 1);
    gather2_kernel<<<(N + 7) / 8, 256>>>(rp, colp, h2, as2p, ad2p, b2, Ws, bs, out, N);
}

// round 13
// speedup vs baseline: 1.0057x; 1.0057x over previous
#include <cuda_runtime.h>
#include <cstdint>

// ---------------------------------------------------------------------------
// Fixed dataset: N=50000, E=800000, IN=128, L1: 4 heads x 64, L2: 1 head x 64.
// edge_index is int32: ei[0:E]=src, ei[E:2E]=dst. Self-loops handled in-warp.
// ---------------------------------------------------------------------------
#define NMAX 50000
#define EMAX 810000

__device__ __align__(16) float g_h1 [NMAX * 256];  // layer1 linear output
__device__ __align__(16) float g_hm [NMAX * 256];  // layer1 GAT output (tf32-rounded)
__device__ __align__(16) float g_h2 [NMAX * 64];   // layer2 linear output
__device__ __align__(16) float g_w1t[128 * 256];
__device__ __align__(16) float g_w2t[256 * 64];
__device__ __align__(16) float g_as1[NMAX * 4];
__device__ __align__(16) float g_ad1[NMAX * 4];
__device__ __align__(16) float g_as2[NMAX];
__device__ __align__(16) float g_ad2[NMAX];
// CSR by dst
__device__ int g_cnt [NMAX];
__device__ int g_rp  [NMAX + 1];
__device__ int g_cur [NMAX];
__device__ int g_col [EMAX];

__device__ __forceinline__ float lrelu(float x) { return x > 0.f ? x : 0.2f * x; }
__device__ __forceinline__ float elu(float x)   { return x > 0.f ? x : expm1f(x); }
__device__ __forceinline__ uint32_t to_tf32(float x) {
    uint32_t r;
    asm("cvt.rna.tf32.f32 %0, %1;" : "=r"(r) : "f"(x));
    return r;
}
__device__ __forceinline__ float tf32f(float x) { return __uint_as_float(to_tf32(x)); }
__device__ __forceinline__ void cp16(uint32_t saddr, const void* gaddr) {
    asm volatile("cp.async.cg.shared.global [%0], [%1], 16;" :: "r"(saddr), "l"(gaddr));
}
__device__ __forceinline__ uint32_t sm_u32(const void* p) {
    return (uint32_t)__cvta_generic_to_shared(p);
}

// ---------------------------------------------------------------------------
// Pre-round W1, W2 to tf32-canonical fp32 (small, ~5us, off critical path)
// ---------------------------------------------------------------------------
__global__ void cvt_w_kernel(const float* __restrict__ w1, float* __restrict__ w1t, int n14,
                             const float* __restrict__ w2, float* __restrict__ w2t, int n24)
{
    int i = blockIdx.x * blockDim.x + threadIdx.x;
    int stride = gridDim.x * blockDim.x;
    for (int j = i; j < n14; j += stride) {
        float4 v = ((const float4*)w1)[j];
        ((float4*)w1t)[j] = make_float4(tf32f(v.x), tf32f(v.y), tf32f(v.z), tf32f(v.w));
    }
    for (int j = i; j < n24; j += stride) {
        float4 v = ((const float4*)w2)[j];
        ((float4*)w2t)[j] = make_float4(tf32f(v.x), tf32f(v.y), tf32f(v.z), tf32f(v.w));
    }
}

// ---------------------------------------------------------------------------
// CSR build — 4 edges/thread for MLP (count/fill are LDG->ATOMG
// latency-bound: R4 profile showed occ 78%, issue 4.6%).
// ---------------------------------------------------------------------------
__global__ void count_kernel(const int* __restrict__ ei, int* cnt, int E) {
    int i = blockIdx.x * blockDim.x + threadIdx.x;
    int E4 = E >> 2;
    if (i < E4) {
        int4 d = ((const int4*)(ei + E))[i];
        atomicAdd(cnt + d.x, 1);
        atomicAdd(cnt + d.y, 1);
        atomicAdd(cnt + d.z, 1);
        atomicAdd(cnt + d.w, 1);
    } else if (i == E4) {
        for (int e = E4 * 4; e < E; e++) atomicAdd(cnt + ei[E + e], 1);
    }
}

__global__ void scan_kernel(const int* __restrict__ cnt, int* rp, int* cur, int N) {
    __shared__ int sums[1024];
    int t = threadIdx.x;
    int C = (N + 1023) / 1024;
    int b0 = t * C, b1 = min(N, b0 + C);
    int s = 0;
    for (int i = b0; i < b1; i++) s += cnt[i];
    sums[t] = s;
    __syncthreads();
    for (int off = 1; off < 1024; off <<= 1) {
        int v = (t >= off) ? sums[t - off] : 0;
        __syncthreads();
        sums[t] += v;
        __syncthreads();
    }
    int run = (t == 0) ? 0 : sums[t - 1];
    for (int i = b0; i < b1; i++) { rp[i] = run; cur[i] = run; run += cnt[i]; }
    if (b0 < N && b1 == N) rp[N] = run;
}

__global__ void fill_kernel(const int* __restrict__ ei, int* cur, int* col, int E) {
    int i = blockIdx.x * blockDim.x + threadIdx.x;
    int E4 = E >> 2;
    if (i < E4) {
        int4 s = ((const int4*)ei)[i];
        int4 d = ((const int4*)(ei + E))[i];
        int p0 = atomicAdd(cur + d.x, 1);
        int p1 = atomicAdd(cur + d.y, 1);
        int p2 = atomicAdd(cur + d.z, 1);
        int p3 = atomicAdd(cur + d.w, 1);
        col[p0] = s.x; col[p1] = s.y; col[p2] = s.z; col[p3] = s.w;
    } else if (i == E4) {
        for (int e = E4 * 4; e < E; e++) {
            int pos = atomicAdd(cur + ei[E + e], 1);
            col[pos] = ei[e];
        }
    }
}

// ---------------------------------------------------------------------------
// TF32 GEMM, cp.async double-buffered. B must be tf32-canonical fp32.
// CVTA: convert A tiles to tf32 (RNA) in smem after arrival (for raw-fp32 A).
// C[M,Nc] = A[M,K] @ B[K,Nc]. Block 128x64, BK=32, 8 warps, warp tile 32x32.
// Fused attention-scalar epilogue (head = blockIdx.x, 64 channels).
// NOTE: in-GEMM B conversion (no cvt_w) was tried twice (R10, R12) and
// regressed the END-TO-END time by ~68us both times — do not reintroduce.
// ---------------------------------------------------------------------------
#define AKP 36
#define BNP 72
#define A_STAGE (128 * AKP)
#define B_STAGE (32 * BNP)
#define STAGE   (A_STAGE + B_STAGE)
#define GEMM_SMEM (2 * STAGE * 4)

template <bool CVTA>
__global__ __launch_bounds__(256, 3) void tf32_gemm(
    int M, int Nc, int K,
    const float* __restrict__ A, const float* __restrict__ B, float* __restrict__ C,
    const float* __restrict__ att_s, const float* __restrict__ att_d,
    float* __restrict__ asrc, float* __restrict__ adst, int astride)
{
    extern __shared__ uint32_t smem[];
    __shared__ float s_ps[2][128];
    __shared__ float s_pd[2][128];

    const int tid    = threadIdx.x;
    const int lane   = tid & 31;
    const int wid    = tid >> 5;
    const int warp_m = wid & 3;
    const int warp_n = wid >> 2;
    const int bn0    = blockIdx.x * 64;
    const int bm0    = blockIdx.y * 128;

    float acc[2][4][4];
#pragma unroll
    for (int i = 0; i < 2; i++)
#pragma unroll
        for (int j = 0; j < 4; j++)
#pragma unroll
            for (int k = 0; k < 4; k++) acc[i][j][k] = 0.f;

    const int rA = lane >> 2;
    const int cA = lane & 3;

    auto issue = [&](int k0, int p) {
        uint32_t* Asb = smem + p * STAGE;
        uint32_t* Bsb = Asb + A_STAGE;
#pragma unroll
        for (int t = 0; t < 4; t++) {
            int i = tid + t * 256, r = i >> 3, c = (i & 7) * 4;
            int gr = bm0 + r;
            if (gr < M) cp16(sm_u32(&Asb[r * AKP + c]), A + (size_t)gr * K + k0 + c);
            else        *(uint4*)&Asb[r * AKP + c] = make_uint4(0, 0, 0, 0);
        }
#pragma unroll
        for (int t = 0; t < 2; t++) {
            int i = tid + t * 256, r = i >> 4, c = (i & 15) * 4;
            cp16(sm_u32(&Bsb[r * BNP + c]), B + (size_t)(k0 + r) * Nc + bn0 + c);
        }
        asm volatile("cp.async.commit_group;");
    };

    const int T = K / 32;
    issue(0, 0);

    for (int t = 0; t < T; t++) {
        int p = t & 1;
        if (t + 1 < T) {
            issue((t + 1) * 32, 1 - p);
            asm volatile("cp.async.wait_group 1;");
        } else {
            asm volatile("cp.async.wait_group 0;");
        }
        __syncthreads();

        uint32_t* Asb = smem + p * STAGE;
        const uint32_t* Bsb = Asb + A_STAGE;

        if (CVTA) {
            // Round this stage's A tile to tf32 in place (same slots this
            // thread cp.async'd; next stage targets the other buffer).
#pragma unroll
            for (int tt = 0; tt < 4; tt++) {
                int i = tid + tt * 256, r = i >> 3, c = (i & 7) * 4;
                uint4 u = *(uint4*)&Asb[r * AKP + c];
                u.x = to_tf32(__uint_as_float(u.x));
                u.y = to_tf32(__uint_as_float(u.y));
                u.z = to_tf32(__uint_as_float(u.z));
                u.w = to_tf32(__uint_as_float(u.w));
                *(uint4*)&Asb[r * AKP + c] = u;
            }
            __syncthreads();
        }

#pragma unroll
        for (int kk = 0; kk < 32; kk += 8) {
            uint32_t a[2][4];
#pragma unroll
            for (int mf = 0; mf < 2; mf++) {
                int r0 = warp_m * 32 + mf * 16 + rA;
                a[mf][0] = Asb[(r0    ) * AKP + kk + cA];
                a[mf][1] = Asb[(r0 + 8) * AKP + kk + cA];
                a[mf][2] = Asb[(r0    ) * AKP + kk + cA + 4];
                a[mf][3] = Asb[(r0 + 8) * AKP + kk + cA + 4];
            }
            uint32_t b[4][2];
#pragma unroll
            for (int nf = 0; nf < 4; nf++) {
                int n0 = warp_n * 32 + nf * 8 + rA;
                b[nf][0] = Bsb[(kk + cA    ) * BNP + n0];
                b[nf][1] = Bsb[(kk + cA + 4) * BNP + n0];
            }
#pragma unroll
            for (int mf = 0; mf < 2; mf++)
#pragma unroll
                for (int nf = 0; nf < 4; nf++) {
                    asm volatile(
                        "mma.sync.aligned.m16n8k8.row.col.f32.tf32.tf32.f32 "
                        "{%0,%1,%2,%3}, {%4,%5,%6,%7}, {%8,%9}, {%0,%1,%2,%3};"
                        : "+f"(acc[mf][nf][0]), "+f"(acc[mf][nf][1]),
                          "+f"(acc[mf][nf][2]), "+f"(acc[mf][nf][3])
                        : "r"(a[mf][0]), "r"(a[mf][1]), "r"(a[mf][2]), "r"(a[mf][3]),
                          "r"(b[nf][0]), "r"(b[nf][1]));
                }
        }
        __syncthreads();
    }

    // Store C
#pragma unroll
    for (int mf = 0; mf < 2; mf++) {
        int r0 = bm0 + warp_m * 32 + mf * 16 + rA;
#pragma unroll
        for (int nf = 0; nf < 4; nf++) {
            int cc = bn0 + warp_n * 32 + nf * 8 + cA * 2;
            if (r0 < M)
                *(float2*)(C + (size_t)r0 * Nc + cc)
                    = make_float2(acc[mf][nf][0], acc[mf][nf][1]);
            if (r0 + 8 < M)
                *(float2*)(C + (size_t)(r0 + 8) * Nc + cc)
                    = make_float2(acc[mf][nf][2], acc[mf][nf][3]);
        }
    }

    // Fused attention scalars for head blockIdx.x
    const int hb = blockIdx.x * 64;
    float ps[2][2] = {{0.f,0.f},{0.f,0.f}}, pd[2][2] = {{0.f,0.f},{0.f,0.f}};
#pragma unroll
    for (int mf = 0; mf < 2; mf++)
#pragma unroll
        for (int nf = 0; nf < 4; nf++) {
            int cloc = warp_n * 32 + nf * 8 + cA * 2;
            float a_s0 = __ldg(att_s + hb + cloc), a_s1 = __ldg(att_s + hb + cloc + 1);
            float a_d0 = __ldg(att_d + hb + cloc), a_d1 = __ldg(att_d + hb + cloc + 1);
            ps[mf][0] += acc[mf][nf][0] * a_s0 + acc[mf][nf][1] * a_s1;
            ps[mf][1] += acc[mf][nf][2] * a_s0 + acc[mf][nf][3] * a_s1;
            pd[mf][0] += acc[mf][nf][0] * a_d0 + acc[mf][nf][1] * a_d1;
            pd[mf][1] += acc[mf][nf][2] * a_d0 + acc[mf][nf][3] * a_d1;
        }
#pragma unroll
    for (int mf = 0; mf < 2; mf++)
#pragma unroll
        for (int hh = 0; hh < 2; hh++) {
            ps[mf][hh] += __shfl_xor_sync(0xffffffffu, ps[mf][hh], 1);
            ps[mf][hh] += __shfl_xor_sync(0xffffffffu, ps[mf][hh], 2);
            pd[mf][hh] += __shfl_xor_sync(0xffffffffu, pd[mf][hh], 1);
            pd[mf][hh] += __shfl_xor_sync(0xffffffffu, pd[mf][hh], 2);
        }
    if (cA == 0) {
#pragma unroll
        for (int mf = 0; mf < 2; mf++) {
            int r0 = warp_m * 32 + mf * 16 + rA;
            s_ps[warp_n][r0]     = ps[mf][0];
            s_ps[warp_n][r0 + 8] = ps[mf][1];
            s_pd[warp_n][r0]     = pd[mf][0];
            s_pd[warp_n][r0 + 8] = pd[mf][1];
        }
    }
    __syncthreads();
    if (tid < 128) {
        int gr = bm0 + tid;
        if (gr < M) {
            asrc[(size_t)gr * astride + blockIdx.x] = s_ps[0][tid] + s_ps[1][tid];
            adst[(size_t)gr * astride + blockIdx.x] = s_pd[0][tid] + s_pd[1][tid];
        }
    }
}

// ---------------------------------------------------------------------------
// Layer-1 GAT gather: one warp per dst node. Column indices + weights cached
// in smem during phase A; phase B 4-way unrolled for MLP.
// WCAP=128 (20KB smem/block keeps residency ~5 CTA/SM, which measured best).
// ---------------------------------------------------------------------------
#define WCAP 128

__global__ __launch_bounds__(256) void gather1_kernel(
    const int* __restrict__ rp, const int* __restrict__ col,
    const float* __restrict__ h1,
    const float* __restrict__ asrc, const float* __restrict__ adst,
    const float* __restrict__ bias, float* __restrict__ out, int N)
{
    __shared__ float s_w[8][WCAP * 4];
    __shared__ int   s_col[8][WCAP];
    int warp = threadIdx.x >> 5, lane = threadIdx.x & 31;
    int d = blockIdx.x * 8 + warp;
    if (d >= N) return;

    int beg = rp[d];
    int deg = rp[d + 1] - beg;
    int hme = lane & 3;
    float ad_hme = __ldg(adst + (size_t)d * 4 + hme);

    float pden = 0.f;
    int npairs = deg * 4;
    for (int idx = lane; idx < npairs; idx += 32) {
        int e = idx >> 2;
        int s = __ldg(col + beg + e);
        float w = __expf(lrelu(__ldg(asrc + (size_t)s * 4 + hme) + ad_hme));
        if (e < WCAP) {
            s_w[warp][idx] = w;
            if (hme == 0) s_col[warp][e] = s;
        }
        pden += w;
    }
    pden += __shfl_xor_sync(0xffffffffu, pden, 4);
    pden += __shfl_xor_sync(0xffffffffu, pden, 8);
    pden += __shfl_xor_sync(0xffffffffu, pden, 16);
    float w_self = __expf(lrelu(__ldg(asrc + (size_t)d * 4 + hme) + ad_hme));
    float inv_den = 1.f / (pden + w_self + 1e-16f);
    __syncwarp();

    int head = lane >> 3;
    float inv_h   = __shfl_sync(0xffffffffu, inv_den, head);
    float aself_h = __shfl_sync(0xffffffffu, w_self,  head) * inv_h;
    float ad_head = __shfl_sync(0xffffffffu, ad_hme,  head);

    float acc[8];
    {
        const float4* hp = (const float4*)(h1 + (size_t)d * 256 + lane * 8);
        float4 v0 = __ldg(hp), v1 = __ldg(hp + 1);
        acc[0]=aself_h*v0.x; acc[1]=aself_h*v0.y; acc[2]=aself_h*v0.z; acc[3]=aself_h*v0.w;
        acc[4]=aself_h*v1.x; acc[5]=aself_h*v1.y; acc[6]=aself_h*v1.z; acc[7]=aself_h*v1.w;
    }

    if (deg <= WCAP) {
        int e = 0;
        for (; e + 4 <= deg; e += 4) {
            int   sx[4];
            float al[4];
#pragma unroll
            for (int q = 0; q < 4; q++) {
                sx[q] = s_col[warp][e + q];
                al[q] = s_w[warp][(e + q) * 4 + head] * inv_h;
            }
            float4 u0[4], u1[4];
#pragma unroll
            for (int q = 0; q < 4; q++) {
                const float4* hp = (const float4*)(h1 + (size_t)sx[q] * 256 + lane * 8);
                u0[q] = __ldg(hp); u1[q] = __ldg(hp + 1);
            }
#pragma unroll
            for (int q = 0; q < 4; q++) {
                acc[0]+=al[q]*u0[q].x; acc[1]+=al[q]*u0[q].y;
                acc[2]+=al[q]*u0[q].z; acc[3]+=al[q]*u0[q].w;
                acc[4]+=al[q]*u1[q].x; acc[5]+=al[q]*u1[q].y;
                acc[6]+=al[q]*u1[q].z; acc[7]+=al[q]*u1[q].w;
            }
        }
        for (; e < deg; e++) {
            int s = s_col[warp][e];
            float alpha = s_w[warp][e * 4 + head] * inv_h;
            const float4* hp = (const float4*)(h1 + (size_t)s * 256 + lane * 8);
            float4 v0 = __ldg(hp), v1 = __ldg(hp + 1);
            acc[0]+=alpha*v0.x; acc[1]+=alpha*v0.y; acc[2]+=alpha*v0.z; acc[3]+=alpha*v0.w;
            acc[4]+=alpha*v1.x; acc[5]+=alpha*v1.y; acc[6]+=alpha*v1.z; acc[7]+=alpha*v1.w;
        }
    } else {
        for (int e = 0; e < deg; e++) {
            int s = __ldg(col + beg + e);
            float w = (e < WCAP) ? s_w[warp][e * 4 + head]
                                 : __expf(lrelu(__ldg(asrc + (size_t)s * 4 + head) + ad_head));
            float alpha = w * inv_h;
            const float4* hp = (const float4*)(h1 + (size_t)s * 256 + lane * 8);
            float4 v0 = __ldg(hp), v1 = __ldg(hp + 1);
            acc[0]+=alpha*v0.x; acc[1]+=alpha*v0.y; acc[2]+=alpha*v0.z; acc[3]+=alpha*v0.w;
            acc[4]+=alpha*v1.x; acc[5]+=alpha*v1.y; acc[6]+=alpha*v1.z; acc[7]+=alpha*v1.w;
        }
    }

    const float4* bp = (const float4*)(bias + lane * 8);
    float4 b0 = __ldg(bp), b1v = __ldg(bp + 1);
    float4 o0, o1;
    o0.x=tf32f(elu(acc[0]+b0.x));  o0.y=tf32f(elu(acc[1]+b0.y));
    o0.z=tf32f(elu(acc[2]+b0.z));  o0.w=tf32f(elu(acc[3]+b0.w));
    o1.x=tf32f(elu(acc[4]+b1v.x)); o1.y=tf32f(elu(acc[5]+b1v.y));
    o1.z=tf32f(elu(acc[6]+b1v.z)); o1.w=tf32f(elu(acc[7]+b1v.w));
    float4* op = (float4*)(out + (size_t)d * 256 + lane * 8);
    op[0] = o0; op[1] = o1;
}

// ---------------------------------------------------------------------------
// Layer-2 GAT gather + final epilogue.
// ---------------------------------------------------------------------------
__global__ __launch_bounds__(256) void gather2_kernel(
    const int* __restrict__ rp, const int* __restrict__ col,
    const float* __restrict__ h2,
    const float* __restrict__ asrc, const float* __restrict__ adst,
    const float* __restrict__ b2, const float* __restrict__ Ws,
    const float* __restrict__ bs, float* __restrict__ out, int N)
{
    __shared__ float s_w[8][WCAP];
    __shared__ int   s_col[8][WCAP];
    int warp = threadIdx.x >> 5, lane = threadIdx.x & 31;
    int d = blockIdx.x * 8 + warp;
    if (d >= N) return;

    int beg = rp[d];
    int deg = rp[d + 1] - beg;
    float adv = __ldg(adst + d);

    float pden = 0.f;
    for (int e = lane; e < deg; e += 32) {
        int s = __ldg(col + beg + e);
        float w = __expf(lrelu(__ldg(asrc + s) + adv));
        if (e < WCAP) { s_w[warp][e] = w; s_col[warp][e] = s; }
        pden += w;
    }
#pragma unroll
    for (int off = 16; off; off >>= 1) pden += __shfl_xor_sync(0xffffffffu, pden, off);
    float w_self = __expf(lrelu(__ldg(asrc + d) + adv));
    float inv_den = 1.f / (pden + w_self + 1e-16f);
    __syncwarp();

    float2 acc;
    {
        float2 v = __ldg((const float2*)(h2 + (size_t)d * 64) + lane);
        float a = w_self * inv_den;
        acc.x = a * v.x; acc.y = a * v.y;
    }
    if (deg <= WCAP) {
        int e = 0;
        for (; e + 4 <= deg; e += 4) {
            int sx[4]; float al[4]; float2 v[4];
#pragma unroll
            for (int q = 0; q < 4; q++) {
                sx[q] = s_col[warp][e + q];
                al[q] = s_w[warp][e + q] * inv_den;
            }
#pragma unroll
            for (int q = 0; q < 4; q++)
                v[q] = __ldg((const float2*)(h2 + (size_t)sx[q] * 64) + lane);
#pragma unroll
            for (int q = 0; q < 4; q++) {
                acc.x += al[q] * v[q].x; acc.y += al[q] * v[q].y;
            }
        }
        for (; e < deg; e++) {
            int s = s_col[warp][e];
            float alpha = s_w[warp][e] * inv_den;
            float2 v = __ldg((const float2*)(h2 + (size_t)s * 64) + lane);
            acc.x += alpha * v.x; acc.y += alpha * v.y;
        }
    } else {
        for (int e = 0; e < deg; e++) {
            int s = __ldg(col + beg + e);
            float w = (e < WCAP) ? s_w[warp][e]
                                 : __expf(lrelu(__ldg(asrc + s) + adv));
            float alpha = w * inv_den;
            float2 v = __ldg((const float2*)(h2 + (size_t)s * 64) + lane);
            acc.x += alpha * v.x; acc.y += alpha * v.y;
        }
    }
    float o0 = elu(acc.x + __ldg(b2 + lane * 2));
    float o1 = elu(acc.y + __ldg(b2 + lane * 2 + 1));
    *(float2*)(out + (size_t)d * 64 + lane * 2) = make_float2(o0, o1);
    float sc = o0 * __ldg(Ws + lane * 2) + o1 * __ldg(Ws + lane * 2 + 1);
#pragma unroll
    for (int off = 16; off; off >>= 1) sc += __shfl_xor_sync(0xffffffffu, sc, off);
    if (lane == 0) out[(size_t)N * 64 + d] = sc + __ldg(bs);
}

// ---------------------------------------------------------------------------
// Launch
// ---------------------------------------------------------------------------
extern "C" void kernel_launch(void* const* d_in, const int* in_sizes, int n_in,
                              void* d_out, int out_size)
{
    const float* x   = (const float*)d_in[0];
    const int*   ei  = (const int*)d_in[1];
    const float* W1  = (const float*)d_in[2];
    const float* as1 = (const float*)d_in[3];
    const float* ad1 = (const float*)d_in[4];
    const float* b1  = (const float*)d_in[5];
    const float* W2  = (const float*)d_in[6];
    const float* as2 = (const float*)d_in[7];
    const float* ad2 = (const float*)d_in[8];
    const float* b2  = (const float*)d_in[9];
    const float* Ws  = (const float*)d_in[10];
    const float* bs  = (const float*)d_in[11];
    float*       out = (float*)d_out;

    const int N = in_sizes[0] / 128;
    const int E = in_sizes[1] / 2;

    float *h1, *hm, *h2, *w1t, *w2t, *as1p, *ad1p, *as2p, *ad2p;
    int *cnt, *rp, *cur, *colp;
    cudaGetSymbolAddress((void**)&h1,   g_h1);
    cudaGetSymbolAddress((void**)&hm,   g_hm);
    cudaGetSymbolAddress((void**)&h2,   g_h2);
    cudaGetSymbolAddress((void**)&w1t,  g_w1t);
    cudaGetSymbolAddress((void**)&w2t,  g_w2t);
    cudaGetSymbolAddress((void**)&as1p, g_as1);
    cudaGetSymbolAddress((void**)&ad1p, g_ad1);
    cudaGetSymbolAddress((void**)&as2p, g_as2);
    cudaGetSymbolAddress((void**)&ad2p, g_ad2);
    cudaGetSymbolAddress((void**)&cnt,  g_cnt);
    cudaGetSymbolAddress((void**)&rp,   g_rp);
    cudaGetSymbolAddress((void**)&cur,  g_cur);
    cudaGetSymbolAddress((void**)&colp, g_col);

    static cudaStream_t s2 = nullptr;
    static cudaEvent_t evFork = nullptr, evJoin = nullptr;
    static bool attrSet = false;
    if (!s2) {
        cudaStreamCreateWithFlags(&s2, cudaStreamNonBlocking);
        cudaEventCreateWithFlags(&evFork, cudaEventDisableTiming);
        cudaEventCreateWithFlags(&evJoin, cudaEventDisableTiming);
    }
    if (!attrSet) {
        cudaFuncSetAttribute(tf32_gemm<true>,
                             cudaFuncAttributeMaxDynamicSharedMemorySize, GEMM_SMEM);
        cudaFuncSetAttribute(tf32_gemm<false>,
                             cudaFuncAttributeMaxDynamicSharedMemorySize, GEMM_SMEM);
        attrSet = true;
    }

    // Fork: CSR build on s2 (vectorized count/fill), concurrent with
    // weight cvt + layer-1 GEMM on the main stream.
    cudaEventRecord(evFork, 0);
    cudaStreamWaitEvent(s2, evFork, 0);
    cudaMemsetAsync(cnt, 0, (size_t)N * sizeof(int), s2);
    int E4 = E >> 2;
    count_kernel<<<(E4 + 256) / 256, 256, 0, s2>>>(ei, cnt, E);
    scan_kernel<<<1, 1024, 0, s2>>>(cnt, rp, cur, N);
    fill_kernel<<<(E4 + 256) / 256, 256, 0, s2>>>(ei, cur, colp, E);
    cudaEventRecord(evJoin, s2);

    // Pre-round weights only (small); x is converted inside GEMM1 (CVTA).
    cvt_w_kernel<<<96, 256>>>(W1, w1t, 128 * 256 / 4, W2, w2t, 256 * 64 / 4);

    // Layer 1 GEMM (+fused att scalars); A = raw x, rounded in-kernel.
    tf32_gemm<true><<<dim3(4, (N + 127) / 128), 256, GEMM_SMEM>>>(
        N, 256, 128, x, w1t, h1, as1, ad1, as1p, ad1p, 4);

    cudaStreamWaitEvent(0, evJoin, 0);
    gather1_kernel<<<(N + 7) / 8, 256>>>(rp, colp, h1, as1p, ad1p, b1, hm, N);

    // Layer 2: hm already tf32-rounded by gather1.
    tf32_gemm<false><<<dim3(1, (N + 127) / 128), 256, GEMM_SMEM>>>(
        N, 64, 256, hm, w2t, h2, as2, ad2, as2p, ad2p, 1);
    gather2_kernel<<<(N + 7) / 8, 256>>>(rp, colp, h2, as2p, ad2p, b2, Ws, bs, out, N);
}

// round 14
// speedup vs baseline: 1.1258x; 1.1194x over previous
#include <cuda_runtime.h>
#include <cuda_fp16.h>
#include <cstdint>

// ---------------------------------------------------------------------------
// Fixed dataset: N=50000, E=800000, IN=128, L1: 4 heads x 64, L2: 1 head x 64.
// edge_index is int32: ei[0:E]=src, ei[E:2E]=dst. Self-loops handled in-warp.
// LOCKED BY MEASUREMENT: scalar CSR kernels, cvt_w pre-pass, WCAP=128
// (each alternative regressed +66..70us end-to-end; R10/R12/R13).
// ---------------------------------------------------------------------------
#define NMAX 50000
#define EMAX 810000

__device__ __align__(16) __half g_h1h[NMAX * 256]; // layer1 linear out (fp16 payload)
__device__ __align__(16) float  g_hm [NMAX * 256]; // layer1 GAT out (tf32-rounded fp32)
__device__ __align__(16) __half g_h2h[NMAX * 64];  // layer2 linear out (fp16 payload)
__device__ __align__(16) float g_w1t[128 * 256];
__device__ __align__(16) float g_w2t[256 * 64];
__device__ __align__(16) float g_as1[NMAX * 4];
__device__ __align__(16) float g_ad1[NMAX * 4];
__device__ __align__(16) float g_as2[NMAX];
__device__ __align__(16) float g_ad2[NMAX];
// CSR by dst
__device__ int g_cnt [NMAX];
__device__ int g_rp  [NMAX + 1];
__device__ int g_cur [NMAX];
__device__ int g_col [EMAX];

__device__ __forceinline__ float lrelu(float x) { return x > 0.f ? x : 0.2f * x; }
__device__ __forceinline__ float elu(float x)   { return x > 0.f ? x : expm1f(x); }
__device__ __forceinline__ uint32_t to_tf32(float x) {
    uint32_t r;
    asm("cvt.rna.tf32.f32 %0, %1;" : "=r"(r) : "f"(x));
    return r;
}
__device__ __forceinline__ float tf32f(float x) { return __uint_as_float(to_tf32(x)); }
__device__ __forceinline__ void cp16(uint32_t saddr, const void* gaddr) {
    asm volatile("cp.async.cg.shared.global [%0], [%1], 16;" :: "r"(saddr), "l"(gaddr));
}
__device__ __forceinline__ uint32_t sm_u32(const void* p) {
    return (uint32_t)__cvta_generic_to_shared(p);
}

// ---------------------------------------------------------------------------
// Pre-round W1, W2 to tf32-canonical fp32 (small, ~5us, off critical path)
// ---------------------------------------------------------------------------
__global__ void cvt_w_kernel(const float* __restrict__ w1, float* __restrict__ w1t, int n14,
                             const float* __restrict__ w2, float* __restrict__ w2t, int n24)
{
    int i = blockIdx.x * blockDim.x + threadIdx.x;
    int stride = gridDim.x * blockDim.x;
    for (int j = i; j < n14; j += stride) {
        float4 v = ((const float4*)w1)[j];
        ((float4*)w1t)[j] = make_float4(tf32f(v.x), tf32f(v.y), tf32f(v.z), tf32f(v.w));
    }
    for (int j = i; j < n24; j += stride) {
        float4 v = ((const float4*)w2)[j];
        ((float4*)w2t)[j] = make_float4(tf32f(v.x), tf32f(v.y), tf32f(v.z), tf32f(v.w));
    }
}

// ---------------------------------------------------------------------------
// CSR build (scalar — vectorized versions regressed; see header note)
// ---------------------------------------------------------------------------
__global__ void count_kernel(const int* __restrict__ ei, int* cnt, int E) {
    int e = blockIdx.x * blockDim.x + threadIdx.x;
    if (e < E) atomicAdd(cnt + ei[E + e], 1);
}

__global__ void scan_kernel(const int* __restrict__ cnt, int* rp, int* cur, int N) {
    __shared__ int sums[1024];
    int t = threadIdx.x;
    int C = (N + 1023) / 1024;
    int b0 = t * C, b1 = min(N, b0 + C);
    int s = 0;
    for (int i = b0; i < b1; i++) s += cnt[i];
    sums[t] = s;
    __syncthreads();
    for (int off = 1; off < 1024; off <<= 1) {
        int v = (t >= off) ? sums[t - off] : 0;
        __syncthreads();
        sums[t] += v;
        __syncthreads();
    }
    int run = (t == 0) ? 0 : sums[t - 1];
    for (int i = b0; i < b1; i++) { rp[i] = run; cur[i] = run; run += cnt[i]; }
    if (b0 < N && b1 == N) rp[N] = run;
}

__global__ void fill_kernel(const int* __restrict__ ei, int* cur, int* col, int E) {
    int e = blockIdx.x * blockDim.x + threadIdx.x;
    if (e >= E) return;
    int d = ei[E + e];
    int pos = atomicAdd(cur + d, 1);
    col[pos] = ei[e];
}

// ---------------------------------------------------------------------------
// TF32 GEMM, cp.async double-buffered. B must be tf32-canonical fp32.
// CVTA: convert A tiles to tf32 (RNA) in smem after arrival.
// C (fp16) [M,Nc] = A[M,K] @ B[K,Nc]. Block 128x64, BK=32, 8 warps.
// Fused attention-scalar epilogue (head = blockIdx.x, 64 channels).
// ---------------------------------------------------------------------------
#define AKP 36
#define BNP 72
#define A_STAGE (128 * AKP)
#define B_STAGE (32 * BNP)
#define STAGE   (A_STAGE + B_STAGE)
#define GEMM_SMEM (2 * STAGE * 4)

template <bool CVTA>
__global__ __launch_bounds__(256, 3) void tf32_gemm(
    int M, int Nc, int K,
    const float* __restrict__ A, const float* __restrict__ B, __half* __restrict__ C,
    const float* __restrict__ att_s, const float* __restrict__ att_d,
    float* __restrict__ asrc, float* __restrict__ adst, int astride)
{
    extern __shared__ uint32_t smem[];
    __shared__ float s_ps[2][128];
    __shared__ float s_pd[2][128];

    const int tid    = threadIdx.x;
    const int lane   = tid & 31;
    const int wid    = tid >> 5;
    const int warp_m = wid & 3;
    const int warp_n = wid >> 2;
    const int bn0    = blockIdx.x * 64;
    const int bm0    = blockIdx.y * 128;

    float acc[2][4][4];
#pragma unroll
    for (int i = 0; i < 2; i++)
#pragma unroll
        for (int j = 0; j < 4; j++)
#pragma unroll
            for (int k = 0; k < 4; k++) acc[i][j][k] = 0.f;

    const int rA = lane >> 2;
    const int cA = lane & 3;

    auto issue = [&](int k0, int p) {
        uint32_t* Asb = smem + p * STAGE;
        uint32_t* Bsb = Asb + A_STAGE;
#pragma unroll
        for (int t = 0; t < 4; t++) {
            int i = tid + t * 256, r = i >> 3, c = (i & 7) * 4;
            int gr = bm0 + r;
            if (gr < M) cp16(sm_u32(&Asb[r * AKP + c]), A + (size_t)gr * K + k0 + c);
            else        *(uint4*)&Asb[r * AKP + c] = make_uint4(0, 0, 0, 0);
        }
#pragma unroll
        for (int t = 0; t < 2; t++) {
            int i = tid + t * 256, r = i >> 4, c = (i & 15) * 4;
            cp16(sm_u32(&Bsb[r * BNP + c]), B + (size_t)(k0 + r) * Nc + bn0 + c);
        }
        asm volatile("cp.async.commit_group;");
    };

    const int T = K / 32;
    issue(0, 0);

    for (int t = 0; t < T; t++) {
        int p = t & 1;
        if (t + 1 < T) {
            issue((t + 1) * 32, 1 - p);
            asm volatile("cp.async.wait_group 1;");
        } else {
            asm volatile("cp.async.wait_group 0;");
        }
        __syncthreads();

        uint32_t* Asb = smem + p * STAGE;
        const uint32_t* Bsb = Asb + A_STAGE;

        if (CVTA) {
#pragma unroll
            for (int tt = 0; tt < 4; tt++) {
                int i = tid + tt * 256, r = i >> 3, c = (i & 7) * 4;
                uint4 u = *(uint4*)&Asb[r * AKP + c];
                u.x = to_tf32(__uint_as_float(u.x));
                u.y = to_tf32(__uint_as_float(u.y));
                u.z = to_tf32(__uint_as_float(u.z));
                u.w = to_tf32(__uint_as_float(u.w));
                *(uint4*)&Asb[r * AKP + c] = u;
            }
            __syncthreads();
        }

#pragma unroll
        for (int kk = 0; kk < 32; kk += 8) {
            uint32_t a[2][4];
#pragma unroll
            for (int mf = 0; mf < 2; mf++) {
                int r0 = warp_m * 32 + mf * 16 + rA;
                a[mf][0] = Asb[(r0    ) * AKP + kk + cA];
                a[mf][1] = Asb[(r0 + 8) * AKP + kk + cA];
                a[mf][2] = Asb[(r0    ) * AKP + kk + cA + 4];
                a[mf][3] = Asb[(r0 + 8) * AKP + kk + cA + 4];
            }
            uint32_t b[4][2];
#pragma unroll
            for (int nf = 0; nf < 4; nf++) {
                int n0 = warp_n * 32 + nf * 8 + rA;
                b[nf][0] = Bsb[(kk + cA    ) * BNP + n0];
                b[nf][1] = Bsb[(kk + cA + 4) * BNP + n0];
            }
#pragma unroll
            for (int mf = 0; mf < 2; mf++)
#pragma unroll
                for (int nf = 0; nf < 4; nf++) {
                    asm volatile(
                        "mma.sync.aligned.m16n8k8.row.col.f32.tf32.tf32.f32 "
                        "{%0,%1,%2,%3}, {%4,%5,%6,%7}, {%8,%9}, {%0,%1,%2,%3};"
                        : "+f"(acc[mf][nf][0]), "+f"(acc[mf][nf][1]),
                          "+f"(acc[mf][nf][2]), "+f"(acc[mf][nf][3])
                        : "r"(a[mf][0]), "r"(a[mf][1]), "r"(a[mf][2]), "r"(a[mf][3]),
                          "r"(b[nf][0]), "r"(b[nf][1]));
                }
        }
        __syncthreads();
    }

    // Store C as fp16 (message payload for the gather kernels)
#pragma unroll
    for (int mf = 0; mf < 2; mf++) {
        int r0 = bm0 + warp_m * 32 + mf * 16 + rA;
#pragma unroll
        for (int nf = 0; nf < 4; nf++) {
            int cc = bn0 + warp_n * 32 + nf * 8 + cA * 2;
            if (r0 < M)
                *(__half2*)(C + (size_t)r0 * Nc + cc)
                    = __floats2half2_rn(acc[mf][nf][0], acc[mf][nf][1]);
            if (r0 + 8 < M)
                *(__half2*)(C + (size_t)(r0 + 8) * Nc + cc)
                    = __floats2half2_rn(acc[mf][nf][2], acc[mf][nf][3]);
        }
    }

    // Fused attention scalars for head blockIdx.x (from fp32 accumulators)
    const int hb = blockIdx.x * 64;
    float ps[2][2] = {{0.f,0.f},{0.f,0.f}}, pd[2][2] = {{0.f,0.f},{0.f,0.f}};
#pragma unroll
    for (int mf = 0; mf < 2; mf++)
#pragma unroll
        for (int nf = 0; nf < 4; nf++) {
            int cloc = warp_n * 32 + nf * 8 + cA * 2;
            float a_s0 = __ldg(att_s + hb + cloc), a_s1 = __ldg(att_s + hb + cloc + 1);
            float a_d0 = __ldg(att_d + hb + cloc), a_d1 = __ldg(att_d + hb + cloc + 1);
            ps[mf][0] += acc[mf][nf][0] * a_s0 + acc[mf][nf][1] * a_s1;
            ps[mf][1] += acc[mf][nf][2] * a_s0 + acc[mf][nf][3] * a_s1;
            pd[mf][0] += acc[mf][nf][0] * a_d0 + acc[mf][nf][1] * a_d1;
            pd[mf][1] += acc[mf][nf][2] * a_d0 + acc[mf][nf][3] * a_d1;
        }
#pragma unroll
    for (int mf = 0; mf < 2; mf++)
#pragma unroll
        for (int hh = 0; hh < 2; hh++) {
            ps[mf][hh] += __shfl_xor_sync(0xffffffffu, ps[mf][hh], 1);
            ps[mf][hh] += __shfl_xor_sync(0xffffffffu, ps[mf][hh], 2);
            pd[mf][hh] += __shfl_xor_sync(0xffffffffu, pd[mf][hh], 1);
            pd[mf][hh] += __shfl_xor_sync(0xffffffffu, pd[mf][hh], 2);
        }
    if (cA == 0) {
#pragma unroll
        for (int mf = 0; mf < 2; mf++) {
            int r0 = warp_m * 32 + mf * 16 + rA;
            s_ps[warp_n][r0]     = ps[mf][0];
            s_ps[warp_n][r0 + 8] = ps[mf][1];
            s_pd[warp_n][r0]     = pd[mf][0];
            s_pd[warp_n][r0 + 8] = pd[mf][1];
        }
    }
    __syncthreads();
    if (tid < 128) {
        int gr = bm0 + tid;
        if (gr < M) {
            asrc[(size_t)gr * astride + blockIdx.x] = s_ps[0][tid] + s_ps[1][tid];
            adst[(size_t)gr * astride + blockIdx.x] = s_pd[0][tid] + s_pd[1][tid];
        }
    }
}

// ---------------------------------------------------------------------------
// Layer-1 GAT gather: one warp per dst node. h1 payload is fp16 (half traffic);
// accumulation in fp32. Column indices + weights cached in smem.
// WCAP=128 (residency-critical; do not shrink).
// ---------------------------------------------------------------------------
#define WCAP 128

__device__ __forceinline__ void acc8_half(float* acc, uint4 u, float al) {
    float2 f0 = __half22float2(*(__half2*)&u.x);
    float2 f1 = __half22float2(*(__half2*)&u.y);
    float2 f2 = __half22float2(*(__half2*)&u.z);
    float2 f3 = __half22float2(*(__half2*)&u.w);
    acc[0] += al * f0.x; acc[1] += al * f0.y;
    acc[2] += al * f1.x; acc[3] += al * f1.y;
    acc[4] += al * f2.x; acc[5] += al * f2.y;
    acc[6] += al * f3.x; acc[7] += al * f3.y;
}

__global__ __launch_bounds__(256) void gather1_kernel(
    const int* __restrict__ rp, const int* __restrict__ col,
    const __half* __restrict__ h1,
    const float* __restrict__ asrc, const float* __restrict__ adst,
    const float* __restrict__ bias, float* __restrict__ out, int N)
{
    __shared__ float s_w[8][WCAP * 4];
    __shared__ int   s_col[8][WCAP];
    int warp = threadIdx.x >> 5, lane = threadIdx.x & 31;
    int d = blockIdx.x * 8 + warp;
    if (d >= N) return;

    int beg = rp[d];
    int deg = rp[d + 1] - beg;
    int hme = lane & 3;
    float ad_hme = __ldg(adst + (size_t)d * 4 + hme);

    float pden = 0.f;
    int npairs = deg * 4;
    for (int idx = lane; idx < npairs; idx += 32) {
        int e = idx >> 2;
        int s = __ldg(col + beg + e);
        float w = __expf(lrelu(__ldg(asrc + (size_t)s * 4 + hme) + ad_hme));
        if (e < WCAP) {
            s_w[warp][idx] = w;
            if (hme == 0) s_col[warp][e] = s;
        }
        pden += w;
    }
    pden += __shfl_xor_sync(0xffffffffu, pden, 4);
    pden += __shfl_xor_sync(0xffffffffu, pden, 8);
    pden += __shfl_xor_sync(0xffffffffu, pden, 16);
    float w_self = __expf(lrelu(__ldg(asrc + (size_t)d * 4 + hme) + ad_hme));
    float inv_den = 1.f / (pden + w_self + 1e-16f);
    __syncwarp();

    int head = lane >> 3;
    float inv_h   = __shfl_sync(0xffffffffu, inv_den, head);
    float aself_h = __shfl_sync(0xffffffffu, w_self,  head) * inv_h;
    float ad_head = __shfl_sync(0xffffffffu, ad_hme,  head);

    float acc[8] = {0,0,0,0,0,0,0,0};
    {
        uint4 u = __ldg((const uint4*)(h1 + (size_t)d * 256 + lane * 8));
        acc8_half(acc, u, aself_h);
    }

    if (deg <= WCAP) {
        int e = 0;
        for (; e + 4 <= deg; e += 4) {
            int   sx[4];
            float al[4];
#pragma unroll
            for (int q = 0; q < 4; q++) {
                sx[q] = s_col[warp][e + q];
                al[q] = s_w[warp][(e + q) * 4 + head] * inv_h;
            }
            uint4 u[4];
#pragma unroll
            for (int q = 0; q < 4; q++)
                u[q] = __ldg((const uint4*)(h1 + (size_t)sx[q] * 256 + lane * 8));
#pragma unroll
            for (int q = 0; q < 4; q++) acc8_half(acc, u[q], al[q]);
        }
        for (; e < deg; e++) {
            int s = s_col[warp][e];
            float alpha = s_w[warp][e * 4 + head] * inv_h;
            uint4 u = __ldg((const uint4*)(h1 + (size_t)s * 256 + lane * 8));
            acc8_half(acc, u, alpha);
        }
    } else {
        for (int e = 0; e < deg; e++) {
            int s = __ldg(col + beg + e);
            float w = (e < WCAP) ? s_w[warp][e * 4 + head]
                                 : __expf(lrelu(__ldg(asrc + (size_t)s * 4 + head) + ad_head));
            float alpha = w * inv_h;
            uint4 u = __ldg((const uint4*)(h1 + (size_t)s * 256 + lane * 8));
            acc8_half(acc, u, alpha);
        }
    }

    const float4* bp = (const float4*)(bias + lane * 8);
    float4 b0 = __ldg(bp), b1v = __ldg(bp + 1);
    float4 o0, o1;
    o0.x=tf32f(elu(acc[0]+b0.x));  o0.y=tf32f(elu(acc[1]+b0.y));
    o0.z=tf32f(elu(acc[2]+b0.z));  o0.w=tf32f(elu(acc[3]+b0.w));
    o1.x=tf32f(elu(acc[4]+b1v.x)); o1.y=tf32f(elu(acc[5]+b1v.y));
    o1.z=tf32f(elu(acc[6]+b1v.z)); o1.w=tf32f(elu(acc[7]+b1v.w));
    float4* op = (float4*)(out + (size_t)d * 256 + lane * 8);
    op[0] = o0; op[1] = o1;
}

// ---------------------------------------------------------------------------
// Layer-2 GAT gather + final epilogue. h2 payload fp16; fp32 accumulation.
// ---------------------------------------------------------------------------
__global__ __launch_bounds__(256) void gather2_kernel(
    const int* __restrict__ rp, const int* __restrict__ col,
    const __half* __restrict__ h2,
    const float* __restrict__ asrc, const float* __restrict__ adst,
    const float* __restrict__ b2, const float* __restrict__ Ws,
    const float* __restrict__ bs, float* __restrict__ out, int N)
{
    __shared__ float s_w[8][WCAP];
    __shared__ int   s_col[8][WCAP];
    int warp = threadIdx.x >> 5, lane = threadIdx.x & 31;
    int d = blockIdx.x * 8 + warp;
    if (d >= N) return;

    int beg = rp[d];
    int deg = rp[d + 1] - beg;
    float adv = __ldg(adst + d);

    float pden = 0.f;
    for (int e = lane; e < deg; e += 32) {
        int s = __ldg(col + beg + e);
        float w = __expf(lrelu(__ldg(asrc + s) + adv));
        if (e < WCAP) { s_w[warp][e] = w; s_col[warp][e] = s; }
        pden += w;
    }
#pragma unroll
    for (int off = 16; off; off >>= 1) pden += __shfl_xor_sync(0xffffffffu, pden, off);
    float w_self = __expf(lrelu(__ldg(asrc + d) + adv));
    float inv_den = 1.f / (pden + w_self + 1e-16f);
    __syncwarp();

    float2 acc;
    {
        float2 v = __half22float2(__ldg((const __half2*)(h2 + (size_t)d * 64) + lane));
        float a = w_self * inv_den;
        acc.x = a * v.x; acc.y = a * v.y;
    }
    if (deg <= WCAP) {
        int e = 0;
        for (; e + 4 <= deg; e += 4) {
            int sx[4]; float al[4]; __half2 v[4];
#pragma unroll
            for (int q = 0; q < 4; q++) {
                sx[q] = s_col[warp][e + q];
                al[q] = s_w[warp][e + q] * inv_den;
            }
#pragma unroll
            for (int q = 0; q < 4; q++)
                v[q] = __ldg((const __half2*)(h2 + (size_t)sx[q] * 64) + lane);
#pragma unroll
            for (int q = 0; q < 4; q++) {
                float2 f = __half22float2(v[q]);
                acc.x += al[q] * f.x; acc.y += al[q] * f.y;
            }
        }
        for (; e < deg; e++) {
            int s = s_col[warp][e];
            float alpha = s_w[warp][e] * inv_den;
            float2 f = __half22float2(__ldg((const __half2*)(h2 + (size_t)s * 64) + lane));
            acc.x += alpha * f.x; acc.y += alpha * f.y;
        }
    } else {
        for (int e = 0; e < deg; e++) {
            int s = __ldg(col + beg + e);
            float w = (e < WCAP) ? s_w[warp][e]
                                 : __expf(lrelu(__ldg(asrc + s) + adv));
            float alpha = w * inv_den;
            float2 f = __half22float2(__ldg((const __half2*)(h2 + (size_t)s * 64) + lane));
            acc.x += alpha * f.x; acc.y += alpha * f.y;
        }
    }
    float o0 = elu(acc.x + __ldg(b2 + lane * 2));
    float o1 = elu(acc.y + __ldg(b2 + lane * 2 + 1));
    *(float2*)(out + (size_t)d * 64 + lane * 2) = make_float2(o0, o1);
    float sc = o0 * __ldg(Ws + lane * 2) + o1 * __ldg(Ws + lane * 2 + 1);
#pragma unroll
    for (int off = 16; off; off >>= 1) sc += __shfl_xor_sync(0xffffffffu, sc, off);
    if (lane == 0) out[(size_t)N * 64 + d] = sc + __ldg(bs);
}

// ---------------------------------------------------------------------------
// Launch
// ---------------------------------------------------------------------------
extern "C" void kernel_launch(void* const* d_in, const int* in_sizes, int n_in,
                              void* d_out, int out_size)
{
    const float* x   = (const float*)d_in[0];
    const int*   ei  = (const int*)d_in[1];
    const float* W1  = (const float*)d_in[2];
    const float* as1 = (const float*)d_in[3];
    const float* ad1 = (const float*)d_in[4];
    const float* b1  = (const float*)d_in[5];
    const float* W2  = (const float*)d_in[6];
    const float* as2 = (const float*)d_in[7];
    const float* ad2 = (const float*)d_in[8];
    const float* b2  = (const float*)d_in[9];
    const float* Ws  = (const float*)d_in[10];
    const float* bs  = (const float*)d_in[11];
    float*       out = (float*)d_out;

    const int N = in_sizes[0] / 128;
    const int E = in_sizes[1] / 2;

    __half *h1h, *h2h;
    float *hm, *w1t, *w2t, *as1p, *ad1p, *as2p, *ad2p;
    int *cnt, *rp, *cur, *colp;
    cudaGetSymbolAddress((void**)&h1h,  g_h1h);
    cudaGetSymbolAddress((void**)&hm,   g_hm);
    cudaGetSymbolAddress((void**)&h2h,  g_h2h);
    cudaGetSymbolAddress((void**)&w1t,  g_w1t);
    cudaGetSymbolAddress((void**)&w2t,  g_w2t);
    cudaGetSymbolAddress((void**)&as1p, g_as1);
    cudaGetSymbolAddress((void**)&ad1p, g_ad1);
    cudaGetSymbolAddress((void**)&as2p, g_as2);
    cudaGetSymbolAddress((void**)&ad2p, g_ad2);
    cudaGetSymbolAddress((void**)&cnt,  g_cnt);
    cudaGetSymbolAddress((void**)&rp,   g_rp);
    cudaGetSymbolAddress((void**)&cur,  g_cur);
    cudaGetSymbolAddress((void**)&colp, g_col);

    static cudaStream_t s2 = nullptr;
    static cudaEvent_t evFork = nullptr, evJoin = nullptr;
    static bool attrSet = false;
    if (!s2) {
        cudaStreamCreateWithFlags(&s2, cudaStreamNonBlocking);
        cudaEventCreateWithFlags(&evFork, cudaEventDisableTiming);
        cudaEventCreateWithFlags(&evJoin, cudaEventDisableTiming);
    }
    if (!attrSet) {
        cudaFuncSetAttribute(tf32_gemm<true>,
                             cudaFuncAttributeMaxDynamicSharedMemorySize, GEMM_SMEM);
        cudaFuncSetAttribute(tf32_gemm<false>,
                             cudaFuncAttributeMaxDynamicSharedMemorySize, GEMM_SMEM);
        attrSet = true;
    }

    // Fork: CSR build on s2, concurrent with weight cvt + layer-1 GEMM.
    cudaEventRecord(evFork, 0);
    cudaStreamWaitEvent(s2, evFork, 0);
    cudaMemsetAsync(cnt, 0, (size_t)N * sizeof(int), s2);
    count_kernel<<<(E + 255) / 256, 256, 0, s2>>>(ei, cnt, E);
    scan_kernel<<<1, 1024, 0, s2>>>(cnt, rp, cur, N);
    fill_kernel<<<(E + 255) / 256, 256, 0, s2>>>(ei, cur, colp, E);
    cudaEventRecord(evJoin, s2);

    // Pre-round weights only (small); x is converted inside GEMM1 (CVTA).
    cvt_w_kernel<<<96, 256>>>(W1, w1t, 128 * 256 / 4, W2, w2t, 256 * 64 / 4);

    // Layer 1 GEMM (+fused att scalars); A = raw x, rounded in-kernel.
    tf32_gemm<true><<<dim3(4, (N + 127) / 128), 256, GEMM_SMEM>>>(
        N, 256, 128, x, w1t, h1h, as1, ad1, as1p, ad1p, 4);

    cudaStreamWaitEvent(0, evJoin, 0);
    gather1_kernel<<<(N + 7) / 8, 256>>>(rp, colp, h1h, as1p, ad1p, b1, hm, N);

    // Layer 2: hm tf32-rounded fp32 by gather1.
    tf32_gemm<false><<<dim3(1, (N + 127) / 128), 256, GEMM_SMEM>>>(
        N, 64, 256, hm, w2t, h2h, as2, ad2, as2p, ad2p, 1);
    gather2_kernel<<<(N + 7) / 8, 256>>>(rp, colp, h2h, as2p, ad2p, b2, Ws, bs, out, N);
}

// round 15
// speedup vs baseline: 1.4394x; 1.2786x over previous
#include <cuda_runtime.h>
#include <cuda_fp16.h>
#include <cstdint>

// ---------------------------------------------------------------------------
// Fixed dataset: N=50000, E=800000, IN=128, L1: 4 heads x 64, L2: 1 head x 64.
// edge_index is int32: ei[0:E]=src, ei[E:2E]=dst. Self-loops handled in-warp.
// LOCKED BY MEASUREMENT: scalar CSR kernels, cvt_w pre-pass, WCAP=128.
// LESSON (R14): gathers are MLP-bound — keep >=8 independent LDG per
// fast-path iteration. fp16 payload only helps at equal MLP.
// ---------------------------------------------------------------------------
#define NMAX 50000
#define EMAX 810000

__device__ __align__(16) __half g_h1h[NMAX * 256]; // layer1 linear out (fp16 payload)
__device__ __align__(16) float  g_hm [NMAX * 256]; // layer1 GAT out (tf32-rounded fp32)
__device__ __align__(16) __half g_h2h[NMAX * 64];  // layer2 linear out (fp16 payload)
__device__ __align__(16) float g_w1t[128 * 256];
__device__ __align__(16) float g_w2t[256 * 64];
__device__ __align__(16) float g_as1[NMAX * 4];
__device__ __align__(16) float g_ad1[NMAX * 4];
__device__ __align__(16) float g_as2[NMAX];
__device__ __align__(16) float g_ad2[NMAX];
// CSR by dst
__device__ int g_cnt [NMAX];
__device__ int g_rp  [NMAX + 1];
__device__ int g_cur [NMAX];
__device__ int g_col [EMAX];

__device__ __forceinline__ float lrelu(float x) { return x > 0.f ? x : 0.2f * x; }
__device__ __forceinline__ float elu(float x)   { return x > 0.f ? x : expm1f(x); }
__device__ __forceinline__ uint32_t to_tf32(float x) {
    uint32_t r;
    asm("cvt.rna.tf32.f32 %0, %1;" : "=r"(r) : "f"(x));
    return r;
}
__device__ __forceinline__ float tf32f(float x) { return __uint_as_float(to_tf32(x)); }
__device__ __forceinline__ void cp16(uint32_t saddr, const void* gaddr) {
    asm volatile("cp.async.cg.shared.global [%0], [%1], 16;" :: "r"(saddr), "l"(gaddr));
}
__device__ __forceinline__ uint32_t sm_u32(const void* p) {
    return (uint32_t)__cvta_generic_to_shared(p);
}

// ---------------------------------------------------------------------------
// Pre-round W1, W2 to tf32-canonical fp32 (small, ~5us, off critical path)
// ---------------------------------------------------------------------------
__global__ void cvt_w_kernel(const float* __restrict__ w1, float* __restrict__ w1t, int n14,
                             const float* __restrict__ w2, float* __restrict__ w2t, int n24)
{
    int i = blockIdx.x * blockDim.x + threadIdx.x;
    int stride = gridDim.x * blockDim.x;
    for (int j = i; j < n14; j += stride) {
        float4 v = ((const float4*)w1)[j];
        ((float4*)w1t)[j] = make_float4(tf32f(v.x), tf32f(v.y), tf32f(v.z), tf32f(v.w));
    }
    for (int j = i; j < n24; j += stride) {
        float4 v = ((const float4*)w2)[j];
        ((float4*)w2t)[j] = make_float4(tf32f(v.x), tf32f(v.y), tf32f(v.z), tf32f(v.w));
    }
}

// ---------------------------------------------------------------------------
// CSR build (scalar — vectorized versions regressed end-to-end)
// ---------------------------------------------------------------------------
__global__ void count_kernel(const int* __restrict__ ei, int* cnt, int E) {
    int e = blockIdx.x * blockDim.x + threadIdx.x;
    if (e < E) atomicAdd(cnt + ei[E + e], 1);
}

__global__ void scan_kernel(const int* __restrict__ cnt, int* rp, int* cur, int N) {
    __shared__ int sums[1024];
    int t = threadIdx.x;
    int C = (N + 1023) / 1024;
    int b0 = t * C, b1 = min(N, b0 + C);
    int s = 0;
    for (int i = b0; i < b1; i++) s += cnt[i];
    sums[t] = s;
    __syncthreads();
    for (int off = 1; off < 1024; off <<= 1) {
        int v = (t >= off) ? sums[t - off] : 0;
        __syncthreads();
        sums[t] += v;
        __syncthreads();
    }
    int run = (t == 0) ? 0 : sums[t - 1];
    for (int i = b0; i < b1; i++) { rp[i] = run; cur[i] = run; run += cnt[i]; }
    if (b0 < N && b1 == N) rp[N] = run;
}

__global__ void fill_kernel(const int* __restrict__ ei, int* cur, int* col, int E) {
    int e = blockIdx.x * blockDim.x + threadIdx.x;
    if (e >= E) return;
    int d = ei[E + e];
    int pos = atomicAdd(cur + d, 1);
    col[pos] = ei[e];
}

// ---------------------------------------------------------------------------
// TF32 GEMM, cp.async double-buffered. B must be tf32-canonical fp32.
// CVTA: convert A tiles to tf32 (RNA) in smem after arrival.
// C (fp16) [M,Nc] = A[M,K] @ B[K,Nc]. Block 128x64, BK=32, 8 warps.
// Fused attention-scalar epilogue (head = blockIdx.x, 64 channels).
// ---------------------------------------------------------------------------
#define AKP 36
#define BNP 72
#define A_STAGE (128 * AKP)
#define B_STAGE (32 * BNP)
#define STAGE   (A_STAGE + B_STAGE)
#define GEMM_SMEM (2 * STAGE * 4)

template <bool CVTA>
__global__ __launch_bounds__(256, 3) void tf32_gemm(
    int M, int Nc, int K,
    const float* __restrict__ A, const float* __restrict__ B, __half* __restrict__ C,
    const float* __restrict__ att_s, const float* __restrict__ att_d,
    float* __restrict__ asrc, float* __restrict__ adst, int astride)
{
    extern __shared__ uint32_t smem[];
    __shared__ float s_ps[2][128];
    __shared__ float s_pd[2][128];

    const int tid    = threadIdx.x;
    const int lane   = tid & 31;
    const int wid    = tid >> 5;
    const int warp_m = wid & 3;
    const int warp_n = wid >> 2;
    const int bn0    = blockIdx.x * 64;
    const int bm0    = blockIdx.y * 128;

    float acc[2][4][4];
#pragma unroll
    for (int i = 0; i < 2; i++)
#pragma unroll
        for (int j = 0; j < 4; j++)
#pragma unroll
            for (int k = 0; k < 4; k++) acc[i][j][k] = 0.f;

    const int rA = lane >> 2;
    const int cA = lane & 3;

    auto issue = [&](int k0, int p) {
        uint32_t* Asb = smem + p * STAGE;
        uint32_t* Bsb = Asb + A_STAGE;
#pragma unroll
        for (int t = 0; t < 4; t++) {
            int i = tid + t * 256, r = i >> 3, c = (i & 7) * 4;
            int gr = bm0 + r;
            if (gr < M) cp16(sm_u32(&Asb[r * AKP + c]), A + (size_t)gr * K + k0 + c);
            else        *(uint4*)&Asb[r * AKP + c] = make_uint4(0, 0, 0, 0);
        }
#pragma unroll
        for (int t = 0; t < 2; t++) {
            int i = tid + t * 256, r = i >> 4, c = (i & 15) * 4;
            cp16(sm_u32(&Bsb[r * BNP + c]), B + (size_t)(k0 + r) * Nc + bn0 + c);
        }
        asm volatile("cp.async.commit_group;");
    };

    const int T = K / 32;
    issue(0, 0);

    for (int t = 0; t < T; t++) {
        int p = t & 1;
        if (t + 1 < T) {
            issue((t + 1) * 32, 1 - p);
            asm volatile("cp.async.wait_group 1;");
        } else {
            asm volatile("cp.async.wait_group 0;");
        }
        __syncthreads();

        uint32_t* Asb = smem + p * STAGE;
        const uint32_t* Bsb = Asb + A_STAGE;

        if (CVTA) {
#pragma unroll
            for (int tt = 0; tt < 4; tt++) {
                int i = tid + tt * 256, r = i >> 3, c = (i & 7) * 4;
                uint4 u = *(uint4*)&Asb[r * AKP + c];
                u.x = to_tf32(__uint_as_float(u.x));
                u.y = to_tf32(__uint_as_float(u.y));
                u.z = to_tf32(__uint_as_float(u.z));
                u.w = to_tf32(__uint_as_float(u.w));
                *(uint4*)&Asb[r * AKP + c] = u;
            }
            __syncthreads();
        }

#pragma unroll
        for (int kk = 0; kk < 32; kk += 8) {
            uint32_t a[2][4];
#pragma unroll
            for (int mf = 0; mf < 2; mf++) {
                int r0 = warp_m * 32 + mf * 16 + rA;
                a[mf][0] = Asb[(r0    ) * AKP + kk + cA];
                a[mf][1] = Asb[(r0 + 8) * AKP + kk + cA];
                a[mf][2] = Asb[(r0    ) * AKP + kk + cA + 4];
                a[mf][3] = Asb[(r0 + 8) * AKP + kk + cA + 4];
            }
            uint32_t b[4][2];
#pragma unroll
            for (int nf = 0; nf < 4; nf++) {
                int n0 = warp_n * 32 + nf * 8 + rA;
                b[nf][0] = Bsb[(kk + cA    ) * BNP + n0];
                b[nf][1] = Bsb[(kk + cA + 4) * BNP + n0];
            }
#pragma unroll
            for (int mf = 0; mf < 2; mf++)
#pragma unroll
                for (int nf = 0; nf < 4; nf++) {
                    asm volatile(
                        "mma.sync.aligned.m16n8k8.row.col.f32.tf32.tf32.f32 "
                        "{%0,%1,%2,%3}, {%4,%5,%6,%7}, {%8,%9}, {%0,%1,%2,%3};"
                        : "+f"(acc[mf][nf][0]), "+f"(acc[mf][nf][1]),
                          "+f"(acc[mf][nf][2]), "+f"(acc[mf][nf][3])
                        : "r"(a[mf][0]), "r"(a[mf][1]), "r"(a[mf][2]), "r"(a[mf][3]),
                          "r"(b[nf][0]), "r"(b[nf][1]));
                }
        }
        __syncthreads();
    }

    // Store C as fp16 (message payload for the gather kernels)
#pragma unroll
    for (int mf = 0; mf < 2; mf++) {
        int r0 = bm0 + warp_m * 32 + mf * 16 + rA;
#pragma unroll
        for (int nf = 0; nf < 4; nf++) {
            int cc = bn0 + warp_n * 32 + nf * 8 + cA * 2;
            if (r0 < M)
                *(__half2*)(C + (size_t)r0 * Nc + cc)
                    = __floats2half2_rn(acc[mf][nf][0], acc[mf][nf][1]);
            if (r0 + 8 < M)
                *(__half2*)(C + (size_t)(r0 + 8) * Nc + cc)
                    = __floats2half2_rn(acc[mf][nf][2], acc[mf][nf][3]);
        }
    }

    // Fused attention scalars for head blockIdx.x (from fp32 accumulators)
    const int hb = blockIdx.x * 64;
    float ps[2][2] = {{0.f,0.f},{0.f,0.f}}, pd[2][2] = {{0.f,0.f},{0.f,0.f}};
#pragma unroll
    for (int mf = 0; mf < 2; mf++)
#pragma unroll
        for (int nf = 0; nf < 4; nf++) {
            int cloc = warp_n * 32 + nf * 8 + cA * 2;
            float a_s0 = __ldg(att_s + hb + cloc), a_s1 = __ldg(att_s + hb + cloc + 1);
            float a_d0 = __ldg(att_d + hb + cloc), a_d1 = __ldg(att_d + hb + cloc + 1);
            ps[mf][0] += acc[mf][nf][0] * a_s0 + acc[mf][nf][1] * a_s1;
            ps[mf][1] += acc[mf][nf][2] * a_s0 + acc[mf][nf][3] * a_s1;
            pd[mf][0] += acc[mf][nf][0] * a_d0 + acc[mf][nf][1] * a_d1;
            pd[mf][1] += acc[mf][nf][2] * a_d0 + acc[mf][nf][3] * a_d1;
        }
#pragma unroll
    for (int mf = 0; mf < 2; mf++)
#pragma unroll
        for (int hh = 0; hh < 2; hh++) {
            ps[mf][hh] += __shfl_xor_sync(0xffffffffu, ps[mf][hh], 1);
            ps[mf][hh] += __shfl_xor_sync(0xffffffffu, ps[mf][hh], 2);
            pd[mf][hh] += __shfl_xor_sync(0xffffffffu, pd[mf][hh], 1);
            pd[mf][hh] += __shfl_xor_sync(0xffffffffu, pd[mf][hh], 2);
        }
    if (cA == 0) {
#pragma unroll
        for (int mf = 0; mf < 2; mf++) {
            int r0 = warp_m * 32 + mf * 16 + rA;
            s_ps[warp_n][r0]     = ps[mf][0];
            s_ps[warp_n][r0 + 8] = ps[mf][1];
            s_pd[warp_n][r0]     = pd[mf][0];
            s_pd[warp_n][r0 + 8] = pd[mf][1];
        }
    }
    __syncthreads();
    if (tid < 128) {
        int gr = bm0 + tid;
        if (gr < M) {
            asrc[(size_t)gr * astride + blockIdx.x] = s_ps[0][tid] + s_ps[1][tid];
            adst[(size_t)gr * astride + blockIdx.x] = s_pd[0][tid] + s_pd[1][tid];
        }
    }
}

// ---------------------------------------------------------------------------
// Layer-1 GAT gather: one warp per dst node. fp16 payload, fp32 accumulation.
// Fast path unrolled 8 edges/iter => 8 independent LDG.128 in flight (same
// MLP as the fp32 champion, half the bytes). WCAP=128 (residency-critical).
// ---------------------------------------------------------------------------
#define WCAP 128

__device__ __forceinline__ void acc8_half(float* acc, uint4 u, float al) {
    float2 f0 = __half22float2(*(__half2*)&u.x);
    float2 f1 = __half22float2(*(__half2*)&u.y);
    float2 f2 = __half22float2(*(__half2*)&u.z);
    float2 f3 = __half22float2(*(__half2*)&u.w);
    acc[0] += al * f0.x; acc[1] += al * f0.y;
    acc[2] += al * f1.x; acc[3] += al * f1.y;
    acc[4] += al * f2.x; acc[5] += al * f2.y;
    acc[6] += al * f3.x; acc[7] += al * f3.y;
}

__global__ __launch_bounds__(256) void gather1_kernel(
    const int* __restrict__ rp, const int* __restrict__ col,
    const __half* __restrict__ h1,
    const float* __restrict__ asrc, const float* __restrict__ adst,
    const float* __restrict__ bias, float* __restrict__ out, int N)
{
    __shared__ float s_w[8][WCAP * 4];
    __shared__ int   s_col[8][WCAP];
    int warp = threadIdx.x >> 5, lane = threadIdx.x & 31;
    int d = blockIdx.x * 8 + warp;
    if (d >= N) return;

    int beg = rp[d];
    int deg = rp[d + 1] - beg;
    int hme = lane & 3;
    float ad_hme = __ldg(adst + (size_t)d * 4 + hme);

    float pden = 0.f;
    int npairs = deg * 4;
    for (int idx = lane; idx < npairs; idx += 32) {
        int e = idx >> 2;
        int s = __ldg(col + beg + e);
        float w = __expf(lrelu(__ldg(asrc + (size_t)s * 4 + hme) + ad_hme));
        if (e < WCAP) {
            s_w[warp][idx] = w;
            if (hme == 0) s_col[warp][e] = s;
        }
        pden += w;
    }
    pden += __shfl_xor_sync(0xffffffffu, pden, 4);
    pden += __shfl_xor_sync(0xffffffffu, pden, 8);
    pden += __shfl_xor_sync(0xffffffffu, pden, 16);
    float w_self = __expf(lrelu(__ldg(asrc + (size_t)d * 4 + hme) + ad_hme));
    float inv_den = 1.f / (pden + w_self + 1e-16f);
    __syncwarp();

    int head = lane >> 3;
    float inv_h   = __shfl_sync(0xffffffffu, inv_den, head);
    float aself_h = __shfl_sync(0xffffffffu, w_self,  head) * inv_h;
    float ad_head = __shfl_sync(0xffffffffu, ad_hme,  head);

    float acc[8] = {0,0,0,0,0,0,0,0};
    {
        uint4 u = __ldg((const uint4*)(h1 + (size_t)d * 256 + lane * 8));
        acc8_half(acc, u, aself_h);
    }

    if (deg <= WCAP) {
        int e = 0;
        for (; e + 8 <= deg; e += 8) {
            int   sx[8];
            float al[8];
#pragma unroll
            for (int q = 0; q < 8; q++) {
                sx[q] = s_col[warp][e + q];
                al[q] = s_w[warp][(e + q) * 4 + head] * inv_h;
            }
            uint4 u[8];
#pragma unroll
            for (int q = 0; q < 8; q++)
                u[q] = __ldg((const uint4*)(h1 + (size_t)sx[q] * 256 + lane * 8));
#pragma unroll
            for (int q = 0; q < 8; q++) acc8_half(acc, u[q], al[q]);
        }
        for (; e < deg; e++) {
            int s = s_col[warp][e];
            float alpha = s_w[warp][e * 4 + head] * inv_h;
            uint4 u = __ldg((const uint4*)(h1 + (size_t)s * 256 + lane * 8));
            acc8_half(acc, u, alpha);
        }
    } else {
        for (int e = 0; e < deg; e++) {
            int s = __ldg(col + beg + e);
            float w = (e < WCAP) ? s_w[warp][e * 4 + head]
                                 : __expf(lrelu(__ldg(asrc + (size_t)s * 4 + head) + ad_head));
            float alpha = w * inv_h;
            uint4 u = __ldg((const uint4*)(h1 + (size_t)s * 256 + lane * 8));
            acc8_half(acc, u, alpha);
        }
    }

    const float4* bp = (const float4*)(bias + lane * 8);
    float4 b0 = __ldg(bp), b1v = __ldg(bp + 1);
    float4 o0, o1;
    o0.x=tf32f(elu(acc[0]+b0.x));  o0.y=tf32f(elu(acc[1]+b0.y));
    o0.z=tf32f(elu(acc[2]+b0.z));  o0.w=tf32f(elu(acc[3]+b0.w));
    o1.x=tf32f(elu(acc[4]+b1v.x)); o1.y=tf32f(elu(acc[5]+b1v.y));
    o1.z=tf32f(elu(acc[6]+b1v.z)); o1.w=tf32f(elu(acc[7]+b1v.w));
    float4* op = (float4*)(out + (size_t)d * 256 + lane * 8);
    op[0] = o0; op[1] = o1;
}

// ---------------------------------------------------------------------------
// Layer-2 GAT gather + final epilogue. fp16 payload; 8-edge unroll for MLP.
// ---------------------------------------------------------------------------
__global__ __launch_bounds__(256) void gather2_kernel(
    const int* __restrict__ rp, const int* __restrict__ col,
    const __half* __restrict__ h2,
    const float* __restrict__ asrc, const float* __restrict__ adst,
    const float* __restrict__ b2, const float* __restrict__ Ws,
    const float* __restrict__ bs, float* __restrict__ out, int N)
{
    __shared__ float s_w[8][WCAP];
    __shared__ int   s_col[8][WCAP];
    int warp = threadIdx.x >> 5, lane = threadIdx.x & 31;
    int d = blockIdx.x * 8 + warp;
    if (d >= N) return;

    int beg = rp[d];
    int deg = rp[d + 1] - beg;
    float adv = __ldg(adst + d);

    float pden = 0.f;
    for (int e = lane; e < deg; e += 32) {
        int s = __ldg(col + beg + e);
        float w = __expf(lrelu(__ldg(asrc + s) + adv));
        if (e < WCAP) { s_w[warp][e] = w; s_col[warp][e] = s; }
        pden += w;
    }
#pragma unroll
    for (int off = 16; off; off >>= 1) pden += __shfl_xor_sync(0xffffffffu, pden, off);
    float w_self = __expf(lrelu(__ldg(asrc + d) + adv));
    float inv_den = 1.f / (pden + w_self + 1e-16f);
    __syncwarp();

    float2 acc;
    {
        float2 v = __half22float2(__ldg((const __half2*)(h2 + (size_t)d * 64) + lane));
        float a = w_self * inv_den;
        acc.x = a * v.x; acc.y = a * v.y;
    }
    if (deg <= WCAP) {
        int e = 0;
        for (; e + 8 <= deg; e += 8) {
            int sx[8]; float al[8]; __half2 v[8];
#pragma unroll
            for (int q = 0; q < 8; q++) {
                sx[q] = s_col[warp][e + q];
                al[q] = s_w[warp][e + q] * inv_den;
            }
#pragma unroll
            for (int q = 0; q < 8; q++)
                v[q] = __ldg((const __half2*)(h2 + (size_t)sx[q] * 64) + lane);
#pragma unroll
            for (int q = 0; q < 8; q++) {
                float2 f = __half22float2(v[q]);
                acc.x += al[q] * f.x; acc.y += al[q] * f.y;
            }
        }
        for (; e < deg; e++) {
            int s = s_col[warp][e];
            float alpha = s_w[warp][e] * inv_den;
            float2 f = __half22float2(__ldg((const __half2*)(h2 + (size_t)s * 64) + lane));
            acc.x += alpha * f.x; acc.y += alpha * f.y;
        }
    } else {
        for (int e = 0; e < deg; e++) {
            int s = __ldg(col + beg + e);
            float w = (e < WCAP) ? s_w[warp][e]
                                 : __expf(lrelu(__ldg(asrc + s) + adv));
            float alpha = w * inv_den;
            float2 f = __half22float2(__ldg((const __half2*)(h2 + (size_t)s * 64) + lane));
            acc.x += alpha * f.x; acc.y += alpha * f.y;
        }
    }
    float o0 = elu(acc.x + __ldg(b2 + lane * 2));
    float o1 = elu(acc.y + __ldg(b2 + lane * 2 + 1));
    *(float2*)(out + (size_t)d * 64 + lane * 2) = make_float2(o0, o1);
    float sc = o0 * __ldg(Ws + lane * 2) + o1 * __ldg(Ws + lane * 2 + 1);
#pragma unroll
    for (int off = 16; off; off >>= 1) sc += __shfl_xor_sync(0xffffffffu, sc, off);
    if (lane == 0) out[(size_t)N * 64 + d] = sc + __ldg(bs);
}

// ---------------------------------------------------------------------------
// Launch
// ---------------------------------------------------------------------------
extern "C" void kernel_launch(void* const* d_in, const int* in_sizes, int n_in,
                              void* d_out, int out_size)
{
    const float* x   = (const float*)d_in[0];
    const int*   ei  = (const int*)d_in[1];
    const float* W1  = (const float*)d_in[2];
    const float* as1 = (const float*)d_in[3];
    const float* ad1 = (const float*)d_in[4];
    const float* b1  = (const float*)d_in[5];
    const float* W2  = (const float*)d_in[6];
    const float* as2 = (const float*)d_in[7];
    const float* ad2 = (const float*)d_in[8];
    const float* b2  = (const float*)d_in[9];
    const float* Ws  = (const float*)d_in[10];
    const float* bs  = (const float*)d_in[11];
    float*       out = (float*)d_out;

    const int N = in_sizes[0] / 128;
    const int E = in_sizes[1] / 2;

    __half *h1h, *h2h;
    float *hm, *w1t, *w2t, *as1p, *ad1p, *as2p, *ad2p;
    int *cnt, *rp, *cur, *colp;
    cudaGetSymbolAddress((void**)&h1h,  g_h1h);
    cudaGetSymbolAddress((void**)&hm,   g_hm);
    cudaGetSymbolAddress((void**)&h2h,  g_h2h);
    cudaGetSymbolAddress((void**)&w1t,  g_w1t);
    cudaGetSymbolAddress((void**)&w2t,  g_w2t);
    cudaGetSymbolAddress((void**)&as1p, g_as1);
    cudaGetSymbolAddress((void**)&ad1p, g_ad1);
    cudaGetSymbolAddress((void**)&as2p, g_as2);
    cudaGetSymbolAddress((void**)&ad2p, g_ad2);
    cudaGetSymbolAddress((void**)&cnt,  g_cnt);
    cudaGetSymbolAddress((void**)&rp,   g_rp);
    cudaGetSymbolAddress((void**)&cur,  g_cur);
    cudaGetSymbolAddress((void**)&colp, g_col);

    static cudaStream_t s2 = nullptr;
    static cudaEvent_t evFork = nullptr, evJoin = nullptr;
    static bool attrSet = false;
    if (!s2) {
        cudaStreamCreateWithFlags(&s2, cudaStreamNonBlocking);
        cudaEventCreateWithFlags(&evFork, cudaEventDisableTiming);
        cudaEventCreateWithFlags(&evJoin, cudaEventDisableTiming);
    }
    if (!attrSet) {
        cudaFuncSetAttribute(tf32_gemm<true>,
                             cudaFuncAttributeMaxDynamicSharedMemorySize, GEMM_SMEM);
        cudaFuncSetAttribute(tf32_gemm<false>,
                             cudaFuncAttributeMaxDynamicSharedMemorySize, GEMM_SMEM);
        attrSet = true;
    }

    // Fork: CSR build on s2, concurrent with weight cvt + layer-1 GEMM.
    cudaEventRecord(evFork, 0);
    cudaStreamWaitEvent(s2, evFork, 0);
    cudaMemsetAsync(cnt, 0, (size_t)N * sizeof(int), s2);
    count_kernel<<<(E + 255) / 256, 256, 0, s2>>>(ei, cnt, E);
    scan_kernel<<<1, 1024, 0, s2>>>(cnt, rp, cur, N);
    fill_kernel<<<(E + 255) / 256, 256, 0, s2>>>(ei, cur, colp, E);
    cudaEventRecord(evJoin, s2);

    // Pre-round weights only (small); x is converted inside GEMM1 (CVTA).
    cvt_w_kernel<<<96, 256>>>(W1, w1t, 128 * 256 / 4, W2, w2t, 256 * 64 / 4);

    // Layer 1 GEMM (+fused att scalars); A = raw x, rounded in-kernel.
    tf32_gemm<true><<<dim3(4, (N + 127) / 128), 256, GEMM_SMEM>>>(
        N, 256, 128, x, w1t, h1h, as1, ad1, as1p, ad1p, 4);

    cudaStreamWaitEvent(0, evJoin, 0);
    gather1_kernel<<<(N + 7) / 8, 256>>>(rp, colp, h1h, as1p, ad1p, b1, hm, N);

    // Layer 2: hm tf32-rounded fp32 by gather1.
    tf32_gemm<false><<<dim3(1, (N + 127) / 128), 256, GEMM_SMEM>>>(
        N, 64, 256, hm, w2t, h2h, as2, ad2, as2p, ad2p, 1);
    gather2_kernel<<<(N + 7) / 8, 256>>>(rp, colp, h2h, as2p, ad2p, b2, Ws, bs, out, N);
}